// round 2
// baseline (speedup 1.0000x reference)
#include <cuda_runtime.h>
#include <math.h>

#define B_  8
#define C_  128
#define N_  4096
#define C2_ 64

// ---------------- scratch (static __device__, allowed) ----------------
__device__ __align__(16) float g_qk[B_*C2_*N_];     // shared q/k projection [b][o][n]
__device__ __align__(16) float g_v [B_*C2_*N_];     // v projection
__device__ __align__(16) float g_xc[B_*C2_*N_];     // x_c projection
__device__ __align__(16) float g_rowsum[B_*N_];     // softmax row sums s_n
__device__ __align__(16) float g_At[B_*N_*72];      // A'[b][n][o]=v[o,n]/s_n, [64]=1/s_n
__device__ __align__(16) float g_t [B_*C2_*N_];     // t = w_t (x_c - x_r) + b_t
__device__ __align__(16) float g_part[2*64*256];    // BN partial sum/sumsq per block
__device__ __align__(16) float g_bn[128];           // scale[64], shift[64]
__device__ __align__(16) float g_P[(size_t)B_*N_*N_]; // 512MB: exp(energy)

// ---------------- packed fp32x2 helpers ----------------
union U2 { float2 f; unsigned long long u; };

__device__ __forceinline__ void ffma2(unsigned long long &acc, unsigned long long a, unsigned long long b){
    asm("fma.rn.f32x2 %0, %1, %2, %0;" : "+l"(acc) : "l"(a), "l"(b));
}
__device__ __forceinline__ unsigned long long splat2(float x){
    unsigned long long r;
    asm("mov.b64 %0, {%1, %1};" : "=l"(r) : "f"(x));
    return r;
}
__device__ __forceinline__ float2 unpack2(unsigned long long v){
    float2 f; asm("mov.b64 {%0, %1}, %2;" : "=f"(f.x), "=f"(f.y) : "l"(v)); return f;
}

// ================= K1: projections qk, v(+bias), xc =================
// grid (64 n-tiles of 64, B), 256 thr. W (3x64x128) staged in smem; x via LDG(L1).
__global__ void __launch_bounds__(256, 2)
k_proj(const float* __restrict__ x, const float* __restrict__ w_qk,
       const float* __restrict__ w_v, const float* __restrict__ b_v,
       const float* __restrict__ w_x)
{
    extern __shared__ float sm[];           // [192][128]
    int b = blockIdx.y, nt = blockIdx.x;
    int tid = threadIdx.x;
    for (int i = tid; i < 8192; i += 256) {
        sm[i]         = w_qk[i];
        sm[8192 + i]  = w_v[i];
        sm[16384 + i] = w_x[i];
    }
    __syncthreads();
    int ty = tid >> 3, tx = tid & 7;        // rows ty*6..+6 (192), cols tx*8 (64)
    int nb = nt * 64 + tx * 8;
    const float* xp = x + (size_t)b * C_ * N_ + nb;

    unsigned long long acc[6][4];
#pragma unroll
    for (int i = 0; i < 6; i++)
#pragma unroll
        for (int j = 0; j < 4; j++) acc[i][j] = 0ull;

#pragma unroll 4
    for (int k = 0; k < 128; k++) {
        U2 bb[4];
        const float2* xr = (const float2*)(xp + (size_t)k * N_);
#pragma unroll
        for (int j = 0; j < 4; j++) bb[j].f = xr[j];
#pragma unroll
        for (int i = 0; i < 6; i++) {
            unsigned long long a2 = splat2(sm[(ty * 6 + i) * 128 + k]);
#pragma unroll
            for (int j = 0; j < 4; j++) ffma2(acc[i][j], a2, bb[j].u);
        }
    }

#pragma unroll
    for (int i = 0; i < 6; i++) {
        int row = ty * 6 + i;
        float o[8];
#pragma unroll
        for (int j = 0; j < 4; j++) { float2 v = unpack2(acc[i][j]); o[2*j] = v.x; o[2*j+1] = v.y; }
        float* dst;
        if (row < 64) {
            dst = g_qk + ((size_t)(b * 64 + row)) * N_ + nb;
        } else if (row < 128) {
            float bias = b_v[row - 64];
#pragma unroll
            for (int m = 0; m < 8; m++) o[m] += bias;
            dst = g_v + ((size_t)(b * 64 + row - 64)) * N_ + nb;
        } else {
            dst = g_xc + ((size_t)(b * 64 + row - 128)) * N_ + nb;
        }
        *(float4*)dst       = make_float4(o[0], o[1], o[2], o[3]);
        *(float4*)(dst + 4) = make_float4(o[4], o[5], o[6], o[7]);
    }
}

// ================= K2: energy = q^T q, P = exp(E), row sums =================
// grid (32 row-tiles of 128, B). Block owns full row strip -> deterministic rowsum.
__global__ void __launch_bounds__(256, 2)
k_energy()
{
    extern __shared__ float sm[];           // As[64][128] | Bs[64][128]
    float* As = sm;
    float* Bs = sm + 64 * 128;
    int b = blockIdx.y, rt = blockIdx.x;
    int tid = threadIdx.x;
    const float* q = g_qk + (size_t)b * 64 * N_;

    for (int i = tid; i < 64 * 128; i += 256) {
        int o = i >> 7, c = i & 127;
        As[i] = q[(size_t)o * N_ + rt * 128 + c];
    }
    int ty = tid >> 3, tx = tid & 7;        // rows ty*4 (128), cols tx*16 (128)
    float rowpart[4] = {0.f, 0.f, 0.f, 0.f};
    float* Pb = g_P + ((size_t)b << 24);

    for (int ct = 0; ct < 32; ct++) {
        __syncthreads();
        for (int i = tid; i < 64 * 128; i += 256) {
            int o = i >> 7, c = i & 127;
            Bs[i] = q[(size_t)o * N_ + ct * 128 + c];
        }
        __syncthreads();

        unsigned long long acc[4][8];
#pragma unroll
        for (int i = 0; i < 4; i++)
#pragma unroll
            for (int j = 0; j < 8; j++) acc[i][j] = 0ull;

#pragma unroll 4
        for (int k = 0; k < 64; k++) {
            float4 av = *(const float4*)&As[k * 128 + ty * 4];
            unsigned long long a0 = splat2(av.x), a1 = splat2(av.y),
                               a2 = splat2(av.z), a3 = splat2(av.w);
            U2 bb[8];
            const float2* bp = (const float2*)&Bs[k * 128 + tx * 16];
#pragma unroll
            for (int j = 0; j < 8; j++) bb[j].f = bp[j];
#pragma unroll
            for (int j = 0; j < 8; j++) {
                ffma2(acc[0][j], a0, bb[j].u);
                ffma2(acc[1][j], a1, bb[j].u);
                ffma2(acc[2][j], a2, bb[j].u);
                ffma2(acc[3][j], a3, bb[j].u);
            }
        }

#pragma unroll
        for (int i = 0; i < 4; i++) {
            int row = rt * 128 + ty * 4 + i;
            float o[16];
#pragma unroll
            for (int j = 0; j < 8; j++) {
                float2 v = unpack2(acc[i][j]);
                o[2*j]   = __expf(v.x);
                o[2*j+1] = __expf(v.y);
            }
            float s = 0.f;
#pragma unroll
            for (int m = 0; m < 16; m++) s += o[m];
            rowpart[i] += s;
            float* dst = Pb + (size_t)row * N_ + ct * 128 + tx * 16;
            *(float4*)(dst)      = make_float4(o[0],  o[1],  o[2],  o[3]);
            *(float4*)(dst + 4)  = make_float4(o[4],  o[5],  o[6],  o[7]);
            *(float4*)(dst + 8)  = make_float4(o[8],  o[9],  o[10], o[11]);
            *(float4*)(dst + 12) = make_float4(o[12], o[13], o[14], o[15]);
        }
    }

    // deterministic rowsum reduction across tx
    __syncthreads();
    float* red = sm;                        // [128][8]
#pragma unroll
    for (int i = 0; i < 4; i++) red[(ty * 4 + i) * 8 + tx] = rowpart[i];
    __syncthreads();
    if (tid < 128) {
        float s = 0.f;
#pragma unroll
        for (int j = 0; j < 8; j++) s += red[tid * 8 + j];
        g_rowsum[b * N_ + rt * 128 + tid] = s;
    }
}

// ================= K2.5: A'[b][n][o] = v[o,n]/s_n ; [64] = 1/s_n =================
__global__ void k_atbuild()
{
    int idx = blockIdx.x * 256 + threadIdx.x;   // 0..32767 = (b,n)
    int b = idx >> 12, n = idx & 4095;
    float inv = 1.0f / g_rowsum[idx];
    float* dst = g_At + (size_t)idx * 72;
    const float* v = g_v + (size_t)b * 64 * N_ + n;
#pragma unroll 8
    for (int o = 0; o < 64; o++) dst[o] = v[(size_t)o * N_] * inv;
    dst[64] = inv;
#pragma unroll
    for (int o = 65; o < 72; o++) dst[o] = 0.f;
}

// ================= K3: x_ru = A' @ P, colsum, x_r, d, t = w_t d + b_t, BN partials ===
// grid (32 m-tiles of 128, B). Block owns full column strip -> colsum exact in-block.
__global__ void __launch_bounds__(256, 2)
k_attnout(const float* __restrict__ w_t, const float* __restrict__ b_t)
{
    extern __shared__ float sm[];
    float* As = sm;                 // [64][72]   (n rows, o cols)  4608 floats
    float* Ps = sm + 4608;          // [64][128]                    8192 floats
    float* Wt = sm + 12800;         // [64][64]                     4096 floats
    float* Cs = sm + 16896;         // [128]
    int b = blockIdx.y, mt = blockIdx.x;
    int tid = threadIdx.x;

    for (int i = tid; i < 64 * 64; i += 256) Wt[i] = w_t[i];

    int ty = tid >> 3, tx = tid & 7;            // o = ty*2 (64), m = tx*16 (128)
    unsigned long long acc[2][8], cs[8];
#pragma unroll
    for (int j = 0; j < 8; j++) { acc[0][j] = 0ull; acc[1][j] = 0ull; cs[j] = 0ull; }

    const float* Pb = g_P + ((size_t)b << 24) + mt * 128;
    const float* Ab = g_At + (size_t)b * N_ * 72;

    for (int nt = 0; nt < 64; nt++) {
        __syncthreads();
        for (int i = tid; i < 64 * 72; i += 256) As[i] = Ab[(size_t)nt * 64 * 72 + i];
        for (int i = tid; i < 64 * 128; i += 256) {
            int r = i >> 7, c = i & 127;
            Ps[i] = Pb[(size_t)(nt * 64 + r) * N_ + c];
        }
        __syncthreads();

#pragma unroll 4
        for (int k = 0; k < 64; k++) {
            const float* ar = As + k * 72;
            unsigned long long a0 = splat2(ar[ty * 2]), a1 = splat2(ar[ty * 2 + 1]);
            U2 bb[8];
            const float2* bp = (const float2*)(Ps + k * 128 + tx * 16);
#pragma unroll
            for (int j = 0; j < 8; j++) bb[j].f = bp[j];
#pragma unroll
            for (int j = 0; j < 8; j++) {
                ffma2(acc[0][j], a0, bb[j].u);
                ffma2(acc[1][j], a1, bb[j].u);
            }
            if (ty == 0) {
                unsigned long long ai = splat2(ar[64]);
#pragma unroll
                for (int j = 0; j < 8; j++) ffma2(cs[j], ai, bb[j].u);
            }
        }
    }
    __syncthreads();
    if (ty == 0) {
#pragma unroll
        for (int j = 0; j < 8; j++) {
            float2 v = unpack2(cs[j]);
            Cs[tx * 16 + 2 * j]     = v.x;
            Cs[tx * 16 + 2 * j + 1] = v.y;
        }
    }
    __syncthreads();

    // d = x_c - x_ru/(1e-9+colsum) into smem (overlays As/Ps; Wt/Cs untouched)
    float* Ds = sm;                 // [64][132]
    const float* xcb = g_xc + (size_t)b * 64 * N_ + mt * 128;
#pragma unroll
    for (int i = 0; i < 2; i++) {
        int o = ty * 2 + i;
#pragma unroll
        for (int j = 0; j < 8; j++) {
            float2 v = unpack2(acc[i][j]);
            int m0 = tx * 16 + 2 * j;
            float c0 = 1e-9f + Cs[m0], c1 = 1e-9f + Cs[m0 + 1];
            Ds[o * 132 + m0]     = xcb[(size_t)o * N_ + m0]     - v.x / c0;
            Ds[o * 132 + m0 + 1] = xcb[(size_t)o * N_ + m0 + 1] - v.y / c1;
        }
    }
    __syncthreads();

    // t = Wt @ D + b_t
    unsigned long long tac[2][8];
#pragma unroll
    for (int j = 0; j < 8; j++) { tac[0][j] = 0ull; tac[1][j] = 0ull; }
#pragma unroll 4
    for (int k = 0; k < 64; k++) {
        unsigned long long w0 = splat2(Wt[(ty * 2) * 64 + k]);
        unsigned long long w1 = splat2(Wt[(ty * 2 + 1) * 64 + k]);
        U2 bb[8];
        const float2* bp = (const float2*)(Ds + k * 132 + tx * 16);
#pragma unroll
        for (int j = 0; j < 8; j++) bb[j].f = bp[j];
#pragma unroll
        for (int j = 0; j < 8; j++) {
            ffma2(tac[0][j], w0, bb[j].u);
            ffma2(tac[1][j], w1, bb[j].u);
        }
    }

    float tv[2][16];
    float psum[2] = {0.f, 0.f}, psq[2] = {0.f, 0.f};
#pragma unroll
    for (int i = 0; i < 2; i++) {
        int o = ty * 2 + i;
        float bias = b_t[o];
#pragma unroll
        for (int j = 0; j < 8; j++) {
            float2 v = unpack2(tac[i][j]);
            tv[i][2*j]   = v.x + bias;
            tv[i][2*j+1] = v.y + bias;
        }
        float* dst = g_t + (size_t)(b * 64 + o) * N_ + mt * 128 + tx * 16;
#pragma unroll
        for (int j = 0; j < 4; j++)
            *(float4*)(dst + 4 * j) = make_float4(tv[i][4*j], tv[i][4*j+1], tv[i][4*j+2], tv[i][4*j+3]);
#pragma unroll
        for (int m = 0; m < 16; m++) { psum[i] += tv[i][m]; psq[i] += tv[i][m] * tv[i][m]; }
    }

    // deterministic BN partial reduction across tx
    __syncthreads();
    float* R = sm;                  // [64][8] sums, +512 sumsq
#pragma unroll
    for (int i = 0; i < 2; i++) {
        int o = ty * 2 + i;
        R[o * 8 + tx]       = psum[i];
        R[512 + o * 8 + tx] = psq[i];
    }
    __syncthreads();
    if (tid < 64) {
        float ss = 0.f, qq = 0.f;
#pragma unroll
        for (int j = 0; j < 8; j++) { ss += R[tid * 8 + j]; qq += R[512 + tid * 8 + j]; }
        int blk = b * 32 + mt;
        g_part[tid * 256 + blk]            = ss;
        g_part[64 * 256 + tid * 256 + blk] = qq;
    }
}

// ================= K5: BN stats -> scale/shift =================
__global__ void k_bnstats(const float* __restrict__ gamma, const float* __restrict__ beta)
{
    int c = threadIdx.x;
    if (c >= 64) return;
    float s = 0.f, q = 0.f;
    for (int j = 0; j < 256; j++) {
        s += g_part[c * 256 + j];
        q += g_part[64 * 256 + c * 256 + j];
    }
    const float invN = 1.0f / 32768.0f;
    float mean = s * invN;
    float var  = q * invN - mean * mean;
    float sc = gamma[c] * rsqrtf(var + 1e-5f);
    g_bn[c]      = sc;
    g_bn[64 + c] = beta[c] - mean * sc;
}

// ================= K6: out = x_c + relu(scale*t + shift) =================
__global__ void k_final(float* __restrict__ out)
{
    int i4 = blockIdx.x * 256 + threadIdx.x;    // float4 index over 8*64*1024
    if (i4 >= B_ * C2_ * (N_ / 4)) return;
    int ch = (i4 >> 10) & 63;
    float sc = g_bn[ch], sh = g_bn[64 + ch];
    float4 t  = ((const float4*)g_t)[i4];
    float4 xc = ((const float4*)g_xc)[i4];
    float4 r;
    r.x = xc.x + fmaxf(0.f, sc * t.x + sh);
    r.y = xc.y + fmaxf(0.f, sc * t.y + sh);
    r.z = xc.z + fmaxf(0.f, sc * t.z + sh);
    r.w = xc.w + fmaxf(0.f, sc * t.w + sh);
    ((float4*)out)[i4] = r;
}

// ================= launch =================
extern "C" void kernel_launch(void* const* d_in, const int* in_sizes, int n_in,
                              void* d_out, int out_size)
{
    const float* x     = (const float*)d_in[0];
    const float* w_qk  = (const float*)d_in[1];
    const float* w_v   = (const float*)d_in[2];
    const float* b_v   = (const float*)d_in[3];
    const float* w_x   = (const float*)d_in[4];
    const float* w_t   = (const float*)d_in[5];
    const float* b_t   = (const float*)d_in[6];
    const float* gamma = (const float*)d_in[7];
    const float* beta  = (const float*)d_in[8];
    float* out = (float*)d_out;

    cudaFuncSetAttribute(k_proj,    cudaFuncAttributeMaxDynamicSharedMemorySize, 98304);
    cudaFuncSetAttribute(k_energy,  cudaFuncAttributeMaxDynamicSharedMemorySize, 65536);
    cudaFuncSetAttribute(k_attnout, cudaFuncAttributeMaxDynamicSharedMemorySize, 68096);

    k_proj   <<<dim3(64, 8), 256, 98304>>>(x, w_qk, w_v, b_v, w_x);
    k_energy <<<dim3(32, 8), 256, 65536>>>();
    k_atbuild<<<128, 256>>>();
    k_attnout<<<dim3(32, 8), 256, 68096>>>(w_t, b_t);
    k_bnstats<<<1, 64>>>(gamma, beta);
    k_final  <<<2048, 256>>>(out);
}

// round 6
// speedup vs baseline: 2.8614x; 2.8614x over previous
#include <cuda_runtime.h>
#include <cuda_bf16.h>
#include <math.h>

#define B_  8
#define C_  128
#define N_  4096
#define C2_ 64

// ---------------- scratch ----------------
__device__ __align__(16) __nv_bfloat16 g_qs[B_*N_*128];    // [b][n][k] k:0-63 hi, 64-127 lo
__device__ __align__(16) float g_v [B_*C2_*N_];
__device__ __align__(16) float g_xc[B_*C2_*N_];
__device__ __align__(16) float g_rspart[B_*32*32*128];     // rowsum partials (b,nt,mt,row)
__device__ __align__(16) float g_invs[B_*N_];
__device__ __align__(16) __nv_bfloat16 g_av[B_*128*N_];    // [b][r][n] r:0-63 hi(v*invs), 64-127 lo
__device__ __align__(16) float g_t [B_*C2_*N_];
__device__ __align__(16) float g_part[2*64*256];
__device__ __align__(16) float g_bn[128];
__device__ __align__(16) __nv_bfloat16 g_ph[(size_t)B_*N_*N_];  // 256MB hi plane of exp(E)
__device__ __align__(16) __nv_bfloat16 g_pl[(size_t)B_*N_*N_];  // 256MB lo plane

// ---------------- helpers ----------------
__device__ __forceinline__ unsigned smem_u32(const void* p){
    unsigned a; asm("{ .reg .u64 t; cvta.to.shared.u64 t, %1; cvt.u32.u64 %0, t; }" : "=r"(a) : "l"(p)); return a;
}
__device__ __forceinline__ void ldsm_x4(unsigned* r, unsigned addr){
    asm volatile("ldmatrix.sync.aligned.m8n8.x4.shared.b16 {%0,%1,%2,%3}, [%4];"
        : "=r"(r[0]), "=r"(r[1]), "=r"(r[2]), "=r"(r[3]) : "r"(addr));
}
__device__ __forceinline__ void ldsm_x2(unsigned* r, unsigned addr){
    asm volatile("ldmatrix.sync.aligned.m8n8.x2.shared.b16 {%0,%1}, [%2];"
        : "=r"(r[0]), "=r"(r[1]) : "r"(addr));
}
__device__ __forceinline__ void mma16816(float* c, const unsigned* a, const unsigned* b){
    asm volatile("mma.sync.aligned.m16n8k16.row.col.f32.bf16.bf16.f32 "
        "{%0,%1,%2,%3}, {%4,%5,%6,%7}, {%8,%9}, {%0,%1,%2,%3};"
        : "+f"(c[0]), "+f"(c[1]), "+f"(c[2]), "+f"(c[3])
        : "r"(a[0]), "r"(a[1]), "r"(a[2]), "r"(a[3]), "r"(b[0]), "r"(b[1]));
}
__device__ __forceinline__ void cp16(unsigned s, const void* g){
    asm volatile("{ .reg .u64 gp; cvta.to.global.u64 gp, %1; cp.async.cg.shared.global [%0], [gp], 16; }"
        :: "r"(s), "l"(g));
}
#define CP_COMMIT() asm volatile("cp.async.commit_group;" ::: "memory")
#define CP_WAIT(n)  asm volatile("cp.async.wait_group %0;" :: "n"(n) : "memory")

__device__ __forceinline__ unsigned packbf(__nv_bfloat16 a, __nv_bfloat16 b){
    return (unsigned)__bfloat16_as_ushort(a) | ((unsigned)__bfloat16_as_ushort(b) << 16);
}
__device__ __forceinline__ float bf2f(unsigned short u){ return __bfloat162float(__ushort_as_bfloat16(u)); }

union U2 { float2 f; unsigned long long u; };
__device__ __forceinline__ void ffma2(unsigned long long &a, unsigned long long x, unsigned long long y){
    asm("fma.rn.f32x2 %0, %1, %2, %0;" : "+l"(a) : "l"(x), "l"(y));
}
__device__ __forceinline__ unsigned long long splat2(float x){
    unsigned long long r; asm("mov.b64 %0, {%1, %1};" : "=l"(r) : "f"(x)); return r;
}
__device__ __forceinline__ float2 unpack2(unsigned long long v){
    float2 f; asm("mov.b64 {%0, %1}, %2;" : "=f"(f.x), "=f"(f.y) : "l"(v)); return f;
}

// ================= K1: projections -> qk split bf16, v fp32(+bias), xc fp32 =================
__global__ void __launch_bounds__(256, 2)
k_proj(const float* __restrict__ x, const float* __restrict__ w_qk,
       const float* __restrict__ w_v, const float* __restrict__ b_v,
       const float* __restrict__ w_x)
{
    extern __shared__ float sm[];
    int b = blockIdx.y, nt = blockIdx.x;
    int tid = threadIdx.x;
    for (int i = tid; i < 8192; i += 256) {
        sm[i] = w_qk[i]; sm[8192 + i] = w_v[i]; sm[16384 + i] = w_x[i];
    }
    __syncthreads();
    int ty = tid >> 3, tx = tid & 7;
    int nb = nt * 64 + tx * 8;
    const float* xp = x + (size_t)b * C_ * N_ + nb;

    unsigned long long acc[6][4];
#pragma unroll
    for (int i = 0; i < 6; i++)
#pragma unroll
        for (int j = 0; j < 4; j++) acc[i][j] = 0ull;

#pragma unroll 4
    for (int k = 0; k < 128; k++) {
        U2 bb[4];
        const float2* xr = (const float2*)(xp + (size_t)k * N_);
#pragma unroll
        for (int j = 0; j < 4; j++) bb[j].f = xr[j];
#pragma unroll
        for (int i = 0; i < 6; i++) {
            unsigned long long a2 = splat2(sm[(ty * 6 + i) * 128 + k]);
#pragma unroll
            for (int j = 0; j < 4; j++) ffma2(acc[i][j], a2, bb[j].u);
        }
    }

#pragma unroll
    for (int i = 0; i < 6; i++) {
        int row = ty * 6 + i;
        float o[8];
#pragma unroll
        for (int j = 0; j < 4; j++) { float2 v = unpack2(acc[i][j]); o[2*j] = v.x; o[2*j+1] = v.y; }
        if (row < 64) {
#pragma unroll
            for (int m = 0; m < 8; m++) {
                float q = o[m];
                __nv_bfloat16 h = __float2bfloat16(q);
                __nv_bfloat16 l = __float2bfloat16(q - __bfloat162float(h));
                size_t nn = (size_t)b * N_ + nb + m;
                g_qs[nn * 128 + row]      = h;
                g_qs[nn * 128 + 64 + row] = l;
            }
        } else if (row < 128) {
            float bias = b_v[row - 64];
#pragma unroll
            for (int m = 0; m < 8; m++) o[m] += bias;
            float* dst = g_v + ((size_t)(b * 64 + row - 64)) * N_ + nb;
            *(float4*)dst       = make_float4(o[0], o[1], o[2], o[3]);
            *(float4*)(dst + 4) = make_float4(o[4], o[5], o[6], o[7]);
        } else {
            float* dst = g_xc + ((size_t)(b * 64 + row - 128)) * N_ + nb;
            *(float4*)dst       = make_float4(o[0], o[1], o[2], o[3]);
            *(float4*)(dst + 4) = make_float4(o[4], o[5], o[6], o[7]);
        }
    }
}

// ================= K2: E=Q^T Q (mma.sync, split bf16 3-pass), P=exp(E) 2 planes, rowsums ===
// grid (mt=32, nt=32, b=8), 256 thr. Block tile 128(n) x 128(m).
#define K2_AS 0
#define K2_BS 34816
#define K2_SMEM 69632
__global__ void __launch_bounds__(256)
k_energy()
{
    extern __shared__ char smc[];
    unsigned sb = smem_u32(smc);
    int mt = blockIdx.x, nt = blockIdx.y, b = blockIdx.z;
    int tid = threadIdx.x, wid = tid >> 5, lane = tid & 31;

    {   // load As/Bs [128 rows][128 halves], smem stride 136 halves (272B)
        const uint4* asrc = (const uint4*)(g_qs + (size_t)(b * N_ + nt * 128) * 128);
        const uint4* bsrc = (const uint4*)(g_qs + (size_t)(b * N_ + mt * 128) * 128);
        for (int i = tid; i < 2048; i += 256) {
            int row = i >> 4, cc = i & 15;
            *(uint4*)(smc + K2_AS + row * 272 + cc * 16) = asrc[i];
            *(uint4*)(smc + K2_BS + row * 272 + cc * 16) = bsrc[i];
        }
    }
    __syncthreads();

    int wn = wid >> 1, wm = wid & 1;
    int rn = wn * 32, cm = wm * 64;
    float c[2][8][4];
#pragma unroll
    for (int ti = 0; ti < 2; ti++)
#pragma unroll
        for (int tj = 0; tj < 8; tj++)
#pragma unroll
            for (int q = 0; q < 4; q++) c[ti][tj][q] = 0.f;

    const int qa[3] = {0, 0, 1}, qb[3] = {0, 1, 0};
#pragma unroll
    for (int s = 0; s < 12; s++) {
        int grp = s >> 2, km = (s & 3) * 32;            // byte offsets
        int ka = qa[grp] * 128 + km, kb = qb[grp] * 128 + km;
        unsigned a[2][4];
#pragma unroll
        for (int ti = 0; ti < 2; ti++)
            ldsm_x4(a[ti], sb + K2_AS + (rn + ti * 16 + (lane & 15)) * 272 + ka + (lane >> 4) * 16);
#pragma unroll
        for (int tj = 0; tj < 8; tj++) {
            unsigned bb[2];
            ldsm_x2(bb, sb + K2_BS + (cm + tj * 8 + (lane & 7)) * 272 + kb + ((lane >> 3) & 1) * 16);
            mma16816(c[0][tj], a[0], bb);
            mma16816(c[1][tj], a[1], bb);
        }
    }

    // epilogue: exp, split hi/lo, store planes, rowsum partials
    float rsA[2] = {0.f, 0.f}, rsB[2] = {0.f, 0.f};
    size_t prow = (size_t)(b * N_ + nt * 128) * N_ + mt * 128;
#pragma unroll
    for (int ti = 0; ti < 2; ti++) {
        int r0 = rn + ti * 16 + (lane >> 2);
#pragma unroll
        for (int tj = 0; tj < 8; tj++) {
            int c0 = cm + tj * 8 + 2 * (lane & 3);
            float p0 = __expf(c[ti][tj][0]), p1 = __expf(c[ti][tj][1]);
            float p2 = __expf(c[ti][tj][2]), p3 = __expf(c[ti][tj][3]);
            rsA[ti] += p0 + p1;  rsB[ti] += p2 + p3;
            __nv_bfloat16 h0 = __float2bfloat16(p0), h1 = __float2bfloat16(p1);
            __nv_bfloat16 h2 = __float2bfloat16(p2), h3 = __float2bfloat16(p3);
            __nv_bfloat16 l0 = __float2bfloat16(p0 - __bfloat162float(h0));
            __nv_bfloat16 l1 = __float2bfloat16(p1 - __bfloat162float(h1));
            __nv_bfloat16 l2 = __float2bfloat16(p2 - __bfloat162float(h2));
            __nv_bfloat16 l3 = __float2bfloat16(p3 - __bfloat162float(h3));
            size_t ba = prow + (size_t)r0 * N_ + c0;
            size_t bc = ba + (size_t)8 * N_;
            *(unsigned*)(g_ph + ba) = packbf(h0, h1);
            *(unsigned*)(g_pl + ba) = packbf(l0, l1);
            *(unsigned*)(g_ph + bc) = packbf(h2, h3);
            *(unsigned*)(g_pl + bc) = packbf(l2, l3);
        }
    }
    __syncthreads();
    float* red = (float*)smc;          // [128][8]
#pragma unroll
    for (int ti = 0; ti < 2; ti++) {
        int r0 = rn + ti * 16 + (lane >> 2);
        red[r0 * 8 + wm * 4 + (lane & 3)]       = rsA[ti];
        red[(r0 + 8) * 8 + wm * 4 + (lane & 3)] = rsB[ti];
    }
    __syncthreads();
    if (tid < 128) {
        float s = 0.f;
#pragma unroll
        for (int j = 0; j < 8; j++) s += red[tid * 8 + j];
        g_rspart[((size_t)(b * 32 + nt) * 32 + mt) * 128 + tid] = s;
    }
}

// ================= K2.6: reduce rowsums -> invs =================
__global__ void k_rowred()
{
    int idx = blockIdx.x * 256 + threadIdx.x;    // (b,n)
    int b = idx >> 12, n = idx & 4095;
    float s = 0.f;
    const float* p = g_rspart + ((size_t)(b * 32 + (n >> 7)) * 32) * 128 + (n & 127);
#pragma unroll
    for (int mt = 0; mt < 32; mt++) s += p[mt * 128];
    g_invs[idx] = 1.0f / s;
}

// ================= K2.7: Av = v * invs, split hi/lo bf16 =================
__global__ void k_avbuild()
{
    int idx = blockIdx.x * 256 + threadIdx.x;    // 8*64*4096
    int b = idx >> 18, o = (idx >> 12) & 63, n = idx & 4095;
    float a = g_v[(size_t)(b * 64 + o) * N_ + n] * g_invs[b * N_ + n];
    __nv_bfloat16 h = __float2bfloat16(a);
    __nv_bfloat16 l = __float2bfloat16(a - __bfloat162float(h));
    g_av[(size_t)(b * 128 + o) * N_ + n]      = h;
    g_av[(size_t)(b * 128 + 64 + o) * N_ + n] = l;
}

// ================= K3: D = Av @ (Ph+Pl) via mma.sync + cp.async pipeline; fused epilogue ===
// grid (mt=32, b=8), 256 thr. Block: M=128 Av rows x 128 m-cols, K=4096 x 2 planes.
#define K3_ST   1024
#define K3_STSZ 55296
#define K3_INV  (1024 + 2*55296)        // 111616
#define K3_WT   (K3_INV + 16384)        // 128000
#define K3_CS   (K3_WT + 16384)         // 144384
#define K3_RED  (K3_CS + 512)           // 144896
#define K3_SMEM (K3_RED + 2048)         // 146944
__device__ __forceinline__ void k3_issue(char* smc, unsigned sb, int st, int b, int mt, int nb, int tid)
{
    unsigned s0 = sb + K3_ST + st * K3_STSZ;
    const __nv_bfloat16* asrc = g_av + (size_t)b * 128 * N_ + nb;
    const __nv_bfloat16* hsrc = g_ph + ((size_t)(b * N_ + mt * 128)) * N_ + nb;
    const __nv_bfloat16* lsrc = g_pl + ((size_t)(b * N_ + mt * 128)) * N_ + nb;
    for (int i = tid; i < 1024; i += 256) {
        int row = i >> 3, cc = i & 7;
        unsigned doff = row * 144 + cc * 16;
        size_t soff = (size_t)row * N_ + cc * 8;
        cp16(s0 + doff,         asrc + soff);
        cp16(s0 + 18432 + doff, hsrc + soff);
        cp16(s0 + 36864 + doff, lsrc + soff);
    }
}

__global__ void __launch_bounds__(256)
k_attn(const float* __restrict__ w_t, const float* __restrict__ b_t)
{
    extern __shared__ char smc[];
    unsigned sb = smem_u32(smc);
    int mt = blockIdx.x, b = blockIdx.y;
    int tid = threadIdx.x, wid = tid >> 5, lane = tid & 31;
    float* invs = (float*)(smc + K3_INV);
    float* Wts  = (float*)(smc + K3_WT);
    float* cs   = (float*)(smc + K3_CS);

    for (int i = tid; i < 4096; i += 256) { invs[i] = g_invs[b * N_ + i]; Wts[i] = w_t[i]; }
    if (tid < 128) cs[tid] = 0.f;

    int wn = wid >> 1, wm = wid & 1;
    int rn = wn * 32, cm = wm * 64;
    float c[2][8][4];
#pragma unroll
    for (int ti = 0; ti < 2; ti++)
#pragma unroll
        for (int tj = 0; tj < 8; tj++)
#pragma unroll
            for (int q = 0; q < 4; q++) c[ti][tj][q] = 0.f;

    k3_issue(smc, sb, 0, b, mt, 0, tid);
    CP_COMMIT();

    for (int ch = 0; ch < 64; ch++) {
        int nb = ch * 64;
        if (ch < 63) { k3_issue(smc, sb, (ch + 1) & 1, b, mt, (ch + 1) * 64, tid); CP_COMMIT(); CP_WAIT(1); }
        else CP_WAIT(0);
        __syncthreads();

        unsigned sA = sb + K3_ST + (ch & 1) * K3_STSZ;
        unsigned sH = sA + 18432, sL = sA + 36864;
#pragma unroll
        for (int ks = 0; ks < 4; ks++) {
            unsigned a[2][4];
#pragma unroll
            for (int ti = 0; ti < 2; ti++)
                ldsm_x4(a[ti], sA + (rn + ti * 16 + (lane & 15)) * 144 + ks * 32 + (lane >> 4) * 16);
#pragma unroll
            for (int tj = 0; tj < 8; tj++) {
                unsigned bh[2], bl[2];
                unsigned boff = (cm + tj * 8 + (lane & 7)) * 144 + ks * 32 + ((lane >> 3) & 1) * 16;
                ldsm_x2(bh, sH + boff);
                ldsm_x2(bl, sL + boff);
                mma16816(c[0][tj], a[0], bh);
                mma16816(c[1][tj], a[1], bh);
                mma16816(c[0][tj], a[0], bl);
                mma16816(c[1][tj], a[1], bl);
            }
        }
        // colsum partial: cs[m] += sum_k invs[nb+k]*(Ph+Pl)[m][k]
        if (tid < 128) {
            char* pH = smc + K3_ST + (ch & 1) * K3_STSZ + 18432;
            char* pL = pH + 18432;
            const float* iv = invs + nb;
            float part = 0.f;
#pragma unroll 4
            for (int k = 0; k < 64; k += 2) {
                unsigned hv = *(const unsigned*)(pH + tid * 144 + 2 * k);
                unsigned lv = *(const unsigned*)(pL + tid * 144 + 2 * k);
                part += (bf2f((unsigned short)hv) + bf2f((unsigned short)lv)) * iv[k]
                      + (bf2f((unsigned short)(hv >> 16)) + bf2f((unsigned short)(lv >> 16))) * iv[k + 1];
            }
            cs[tid] += part;
        }
        __syncthreads();
    }

    // frags -> Ds smem [128][132]
    float* Ds = (float*)(smc + K3_ST);
#pragma unroll
    for (int ti = 0; ti < 2; ti++) {
        int r0 = rn + ti * 16 + (lane >> 2);
#pragma unroll
        for (int tj = 0; tj < 8; tj++) {
            int c0 = cm + tj * 8 + 2 * (lane & 3);
            *(float2*)&Ds[r0 * 132 + c0]       = make_float2(c[ti][tj][0], c[ti][tj][1]);
            *(float2*)&Ds[(r0 + 8) * 132 + c0] = make_float2(c[ti][tj][2], c[ti][tj][3]);
        }
    }
    __syncthreads();

    // d = x_c - (D[o]+D[o+64])/(1e-9+cs)
    int o = tid >> 2, g = tid & 3;
    {
        const float* xcb = g_xc + (size_t)(b * 64 + o) * N_ + mt * 128;
#pragma unroll 4
        for (int k = 0; k < 32; k++) {
            int m = g * 32 + k;
            float xru = Ds[o * 132 + m] + Ds[(o + 64) * 132 + m];
            Ds[o * 132 + m] = xcb[m] - xru / (1e-9f + cs[m]);
        }
    }
    __syncthreads();

    // t = Wt @ d + b_t ; BN partials
    {
        float bias = b_t[o];
        float psum = 0.f, psq = 0.f;
        float* tout = g_t + (size_t)(b * 64 + o) * N_ + mt * 128;
#pragma unroll
        for (int rep = 0; rep < 2; rep++) {
            int m0 = g * 32 + rep * 16;
            float acc[16];
#pragma unroll
            for (int j = 0; j < 16; j++) acc[j] = 0.f;
#pragma unroll 4
            for (int k = 0; k < 64; k++) {
                float w = Wts[o * 64 + k];
                const float4* dr = (const float4*)&Ds[k * 132 + m0];
#pragma unroll
                for (int q = 0; q < 4; q++) {
                    float4 d4 = dr[q];
                    acc[4*q]   += w * d4.x; acc[4*q+1] += w * d4.y;
                    acc[4*q+2] += w * d4.z; acc[4*q+3] += w * d4.w;
                }
            }
#pragma unroll
            for (int j = 0; j < 16; j += 4) {
                float t0 = acc[j] + bias, t1 = acc[j+1] + bias, t2 = acc[j+2] + bias, t3 = acc[j+3] + bias;
                *(float4*)&tout[m0 + j] = make_float4(t0, t1, t2, t3);
                psum += t0 + t1 + t2 + t3;
                psq  += t0*t0 + t1*t1 + t2*t2 + t3*t3;
            }
        }
        float* Rs = (float*)(smc + K3_RED);
        float* Rq = Rs + 256;
        Rs[o * 4 + g] = psum;
        Rq[o * 4 + g] = psq;
        __syncthreads();
        if (tid < 64) {
            float s = Rs[tid*4] + Rs[tid*4+1] + Rs[tid*4+2] + Rs[tid*4+3];
            float q = Rq[tid*4] + Rq[tid*4+1] + Rq[tid*4+2] + Rq[tid*4+3];
            int blk = b * 32 + mt;
            g_part[tid * 256 + blk]            = s;
            g_part[64 * 256 + tid * 256 + blk] = q;
        }
    }
}

// ================= K5: BN stats =================
__global__ void k_bnstats(const float* __restrict__ gamma, const float* __restrict__ beta)
{
    int c = threadIdx.x;
    if (c >= 64) return;
    float s = 0.f, q = 0.f;
    for (int j = 0; j < 256; j++) {
        s += g_part[c * 256 + j];
        q += g_part[64 * 256 + c * 256 + j];
    }
    const float invN = 1.0f / 32768.0f;
    float mean = s * invN;
    float var  = q * invN - mean * mean;
    float sc = gamma[c] * rsqrtf(var + 1e-5f);
    g_bn[c]      = sc;
    g_bn[64 + c] = beta[c] - mean * sc;
}

// ================= K6: out = x_c + relu(scale*t + shift) =================
__global__ void k_final(float* __restrict__ out)
{
    int i4 = blockIdx.x * 256 + threadIdx.x;
    if (i4 >= B_ * C2_ * (N_ / 4)) return;
    int ch = (i4 >> 10) & 63;
    float sc = g_bn[ch], sh = g_bn[64 + ch];
    float4 t  = ((const float4*)g_t)[i4];
    float4 xc = ((const float4*)g_xc)[i4];
    float4 r;
    r.x = xc.x + fmaxf(0.f, sc * t.x + sh);
    r.y = xc.y + fmaxf(0.f, sc * t.y + sh);
    r.z = xc.z + fmaxf(0.f, sc * t.z + sh);
    r.w = xc.w + fmaxf(0.f, sc * t.w + sh);
    ((float4*)out)[i4] = r;
}

// ================= launch =================
extern "C" void kernel_launch(void* const* d_in, const int* in_sizes, int n_in,
                              void* d_out, int out_size)
{
    const float* x     = (const float*)d_in[0];
    const float* w_qk  = (const float*)d_in[1];
    const float* w_v   = (const float*)d_in[2];
    const float* b_v   = (const float*)d_in[3];
    const float* w_x   = (const float*)d_in[4];
    const float* w_t   = (const float*)d_in[5];
    const float* b_t   = (const float*)d_in[6];
    const float* gamma = (const float*)d_in[7];
    const float* beta  = (const float*)d_in[8];
    float* out = (float*)d_out;

    cudaFuncSetAttribute(k_proj,   cudaFuncAttributeMaxDynamicSharedMemorySize, 98304);
    cudaFuncSetAttribute(k_energy, cudaFuncAttributeMaxDynamicSharedMemorySize, K2_SMEM);
    cudaFuncSetAttribute(k_attn,   cudaFuncAttributeMaxDynamicSharedMemorySize, K3_SMEM);

    k_proj    <<<dim3(64, 8), 256, 98304>>>(x, w_qk, w_v, b_v, w_x);
    k_energy  <<<dim3(32, 32, 8), 256, K2_SMEM>>>();
    k_rowred  <<<128, 256>>>();
    k_avbuild <<<8192, 256>>>();
    k_attn    <<<dim3(32, 8), 256, K3_SMEM>>>(w_t, b_t);
    k_bnstats <<<1, 64>>>(gamma, beta);
    k_final   <<<2048, 256>>>(out);
}

// round 8
// speedup vs baseline: 4.9333x; 1.7241x over previous
#include <cuda_runtime.h>
#include <cuda_bf16.h>
#include <math.h>

#define B_  8
#define C_  128
#define N_  4096
#define C2_ 64

// ---------------- scratch ----------------
__device__ __align__(16) __nv_bfloat16 g_qs[B_*N_*128];    // [b][n][k] k:0-63 hi, 64-127 lo
__device__ __align__(16) float g_v [B_*C2_*N_];
__device__ __align__(16) float g_xc[B_*C2_*N_];
__device__ __align__(16) float g_rspart[B_*32*32*128];     // rowsum partials (b,nt,mt,row)
__device__ __align__(16) float g_invs[B_*N_];
__device__ __align__(16) __nv_bfloat16 g_invsbf[B_*2*N_];  // [b][hi/lo][n]
__device__ __align__(16) __nv_bfloat16 g_av[B_*128*N_];    // [b][r][n] r:0-63 hi(v*invs), 64-127 lo
__device__ __align__(16) float g_t [B_*C2_*N_];
__device__ __align__(16) float g_part[2*64*256];
__device__ __align__(16) float g_bn[128];
__device__ __align__(16) __nv_bfloat16 g_ph[(size_t)B_*N_*N_];  // 256MB hi plane of exp(E)
__device__ __align__(16) __nv_bfloat16 g_pl[(size_t)B_*N_*N_];  // 256MB lo plane

// ---------------- helpers ----------------
__device__ __forceinline__ unsigned smem_u32(const void* p){
    unsigned a; asm("{ .reg .u64 t; cvta.to.shared.u64 t, %1; cvt.u32.u64 %0, t; }" : "=r"(a) : "l"(p)); return a;
}
__device__ __forceinline__ void ldsm_x4(unsigned* r, unsigned addr){
    asm volatile("ldmatrix.sync.aligned.m8n8.x4.shared.b16 {%0,%1,%2,%3}, [%4];"
        : "=r"(r[0]), "=r"(r[1]), "=r"(r[2]), "=r"(r[3]) : "r"(addr));
}
__device__ __forceinline__ void mma16816(float* c, const unsigned* a, const unsigned* b){
    asm volatile("mma.sync.aligned.m16n8k16.row.col.f32.bf16.bf16.f32 "
        "{%0,%1,%2,%3}, {%4,%5,%6,%7}, {%8,%9}, {%0,%1,%2,%3};"
        : "+f"(c[0]), "+f"(c[1]), "+f"(c[2]), "+f"(c[3])
        : "r"(a[0]), "r"(a[1]), "r"(a[2]), "r"(a[3]), "r"(b[0]), "r"(b[1]));
}
__device__ __forceinline__ void cp16(unsigned s, const void* g){
    asm volatile("{ .reg .u64 gp; cvta.to.global.u64 gp, %1; cp.async.cg.shared.global [%0], [gp], 16; }"
        :: "r"(s), "l"(g));
}
#define CP_COMMIT() asm volatile("cp.async.commit_group;" ::: "memory")
#define CP_WAIT(n)  asm volatile("cp.async.wait_group %0;" :: "n"(n) : "memory")

__device__ __forceinline__ unsigned packbf(__nv_bfloat16 a, __nv_bfloat16 b){
    return (unsigned)__bfloat16_as_ushort(a) | ((unsigned)__bfloat16_as_ushort(b) << 16);
}

union U2 { float2 f; unsigned long long u; };
__device__ __forceinline__ void ffma2(unsigned long long &a, unsigned long long x, unsigned long long y){
    asm("fma.rn.f32x2 %0, %1, %2, %0;" : "+l"(a) : "l"(x), "l"(y));
}
__device__ __forceinline__ unsigned long long splat2(float x){
    unsigned long long r; asm("mov.b64 %0, {%1, %1};" : "=l"(r) : "f"(x)); return r;
}
__device__ __forceinline__ float2 unpack2(unsigned long long v){
    float2 f; asm("mov.b64 {%0, %1}, %2;" : "=f"(f.x), "=f"(f.y) : "l"(v)); return f;
}

// ================= K1: projections -> qk split bf16, v fp32(+bias), xc fp32 =================
__global__ void __launch_bounds__(256, 2)
k_proj(const float* __restrict__ x, const float* __restrict__ w_qk,
       const float* __restrict__ w_v, const float* __restrict__ b_v,
       const float* __restrict__ w_x)
{
    extern __shared__ float sm[];
    int b = blockIdx.y, nt = blockIdx.x;
    int tid = threadIdx.x;
    for (int i = tid; i < 8192; i += 256) {
        sm[i] = w_qk[i]; sm[8192 + i] = w_v[i]; sm[16384 + i] = w_x[i];
    }
    __syncthreads();
    int ty = tid >> 3, tx = tid & 7;
    int nb = nt * 64 + tx * 8;
    const float* xp = x + (size_t)b * C_ * N_ + nb;

    unsigned long long acc[6][4];
#pragma unroll
    for (int i = 0; i < 6; i++)
#pragma unroll
        for (int j = 0; j < 4; j++) acc[i][j] = 0ull;

#pragma unroll 4
    for (int k = 0; k < 128; k++) {
        U2 bb[4];
        const float2* xr = (const float2*)(xp + (size_t)k * N_);
#pragma unroll
        for (int j = 0; j < 4; j++) bb[j].f = xr[j];
#pragma unroll
        for (int i = 0; i < 6; i++) {
            unsigned long long a2 = splat2(sm[(ty * 6 + i) * 128 + k]);
#pragma unroll
            for (int j = 0; j < 4; j++) ffma2(acc[i][j], a2, bb[j].u);
        }
    }

#pragma unroll
    for (int i = 0; i < 6; i++) {
        int row = ty * 6 + i;
        float o[8];
#pragma unroll
        for (int j = 0; j < 4; j++) { float2 v = unpack2(acc[i][j]); o[2*j] = v.x; o[2*j+1] = v.y; }
        if (row < 64) {
#pragma unroll
            for (int m = 0; m < 8; m++) {
                float q = o[m];
                __nv_bfloat16 h = __float2bfloat16(q);
                __nv_bfloat16 l = __float2bfloat16(q - __bfloat162float(h));
                size_t nn = (size_t)b * N_ + nb + m;
                g_qs[nn * 128 + row]      = h;
                g_qs[nn * 128 + 64 + row] = l;
            }
        } else if (row < 128) {
            float bias = b_v[row - 64];
#pragma unroll
            for (int m = 0; m < 8; m++) o[m] += bias;
            float* dst = g_v + ((size_t)(b * 64 + row - 64)) * N_ + nb;
            *(float4*)dst       = make_float4(o[0], o[1], o[2], o[3]);
            *(float4*)(dst + 4) = make_float4(o[4], o[5], o[6], o[7]);
        } else {
            float* dst = g_xc + ((size_t)(b * 64 + row - 128)) * N_ + nb;
            *(float4*)dst       = make_float4(o[0], o[1], o[2], o[3]);
            *(float4*)(dst + 4) = make_float4(o[4], o[5], o[6], o[7]);
        }
    }
}

// ================= K2: symmetric E=Q^T Q, P=exp(E) planes + mirror, rowsums both sides ===
// grid (528 upper-tri tiles, 8), 256 thr. Tile 128(n) x 128(m), mt >= nt.
#define K2_AS 0
#define K2_BS 34816
#define K2_STG 0            // u32 stage [64][129] = 33024 (reuses As)
#define K2_RED 33280        // [128][8] f32 = 4096
#define K2_RDT 37376        // [4][128] f32 = 2048
#define K2_SMEM 69632
__global__ void __launch_bounds__(256)
k_energy()
{
    extern __shared__ char smc[];
    unsigned sb = smem_u32(smc);
    int b = blockIdx.y;
    int tid = threadIdx.x, wid = tid >> 5, lane = tid & 31;

    // triangular decode: blockIdx.x -> (nt, mt) with mt >= nt
    int u = blockIdx.x, nt = 0;
    while (u >= 32 - nt) { u -= 32 - nt; nt++; }
    int mt = nt + u;

    {   // load As (nt rows) / Bs (mt rows): [128 rows][128 halves], stride 272B
        const uint4* asrc = (const uint4*)(g_qs + (size_t)(b * N_ + nt * 128) * 128);
        const uint4* bsrc = (const uint4*)(g_qs + (size_t)(b * N_ + mt * 128) * 128);
        for (int i = tid; i < 2048; i += 256) {
            int row = i >> 4, cc = i & 15;
            *(uint4*)(smc + K2_AS + row * 272 + cc * 16) = asrc[i];
            *(uint4*)(smc + K2_BS + row * 272 + cc * 16) = bsrc[i];
        }
    }
    __syncthreads();

    int wn = wid >> 1, wm = wid & 1;
    int rn = wn * 32, cm = wm * 64;
    float c[2][8][4];
#pragma unroll
    for (int ti = 0; ti < 2; ti++)
#pragma unroll
        for (int tj = 0; tj < 8; tj++)
#pragma unroll
            for (int q = 0; q < 4; q++) c[ti][tj][q] = 0.f;

    const int qa[3] = {0, 0, 1}, qb[3] = {0, 1, 0};
#pragma unroll
    for (int s = 0; s < 12; s++) {
        int grp = s >> 2, km = (s & 3) * 32;
        int ka = qa[grp] * 128 + km, kb = qb[grp] * 128 + km;
        unsigned a[2][4];
#pragma unroll
        for (int ti = 0; ti < 2; ti++)
            ldsm_x4(a[ti], sb + K2_AS + (rn + ti * 16 + (lane & 15)) * 272 + ka + (lane >> 4) * 16);
#pragma unroll
        for (int tjp = 0; tjp < 4; tjp++) {
            unsigned bb[4];
            ldsm_x4(bb, sb + K2_BS + (cm + tjp * 16 + ((lane >> 4) << 3) + (lane & 7)) * 272
                        + kb + ((lane >> 3) & 1) * 16);
            mma16816(c[0][2*tjp],   a[0], bb);     mma16816(c[1][2*tjp],   a[1], bb);
            mma16816(c[0][2*tjp+1], a[0], bb + 2); mma16816(c[1][2*tjp+1], a[1], bb + 2);
        }
    }

    // epilogue pass 1: p=exp, rowpart(nt rows), colpart(mt rows via shuffle), direct stores
    bool offd = (mt != nt);
    float rsA[2] = {0.f, 0.f}, rsB[2] = {0.f, 0.f};
    float colp0[8], colp1[8];
#pragma unroll
    for (int tj = 0; tj < 8; tj++) { colp0[tj] = 0.f; colp1[tj] = 0.f; }
    size_t prow = (size_t)(b * N_ + nt * 128) * N_ + mt * 128;
#pragma unroll
    for (int ti = 0; ti < 2; ti++) {
        int r0 = rn + ti * 16 + (lane >> 2);
#pragma unroll
        for (int tj = 0; tj < 8; tj++) {
            int c0 = cm + tj * 8 + 2 * (lane & 3);
            float p0 = __expf(c[ti][tj][0]), p1 = __expf(c[ti][tj][1]);
            float p2 = __expf(c[ti][tj][2]), p3 = __expf(c[ti][tj][3]);
            c[ti][tj][0] = p0; c[ti][tj][1] = p1; c[ti][tj][2] = p2; c[ti][tj][3] = p3;
            rsA[ti] += p0 + p1;  rsB[ti] += p2 + p3;
            colp0[tj] += p0 + p2; colp1[tj] += p1 + p3;
            __nv_bfloat16 h0 = __float2bfloat16(p0), h1 = __float2bfloat16(p1);
            __nv_bfloat16 h2 = __float2bfloat16(p2), h3 = __float2bfloat16(p3);
            __nv_bfloat16 l0 = __float2bfloat16(p0 - __bfloat162float(h0));
            __nv_bfloat16 l1 = __float2bfloat16(p1 - __bfloat162float(h1));
            __nv_bfloat16 l2 = __float2bfloat16(p2 - __bfloat162float(h2));
            __nv_bfloat16 l3 = __float2bfloat16(p3 - __bfloat162float(h3));
            size_t ba = prow + (size_t)r0 * N_ + c0;
            size_t bc = ba + (size_t)8 * N_;
            *(unsigned*)(g_ph + ba) = packbf(h0, h1);
            *(unsigned*)(g_pl + ba) = packbf(l0, l1);
            *(unsigned*)(g_ph + bc) = packbf(h2, h3);
            *(unsigned*)(g_pl + bc) = packbf(l2, l3);
        }
    }
    if (offd) {
#pragma unroll
        for (int tj = 0; tj < 8; tj++) {
            colp0[tj] += __shfl_xor_sync(0xffffffff, colp0[tj], 4);
            colp0[tj] += __shfl_xor_sync(0xffffffff, colp0[tj], 8);
            colp0[tj] += __shfl_xor_sync(0xffffffff, colp0[tj], 16);
            colp1[tj] += __shfl_xor_sync(0xffffffff, colp1[tj], 4);
            colp1[tj] += __shfl_xor_sync(0xffffffff, colp1[tj], 8);
            colp1[tj] += __shfl_xor_sync(0xffffffff, colp1[tj], 16);
        }
    }
    __syncthreads();   // As/Bs dead; smem reuse begins

    float* red  = (float*)(smc + K2_RED);     // [128][8] nt-row partials
    float* redT = (float*)(smc + K2_RDT);     // [4][128] mt-row partials
#pragma unroll
    for (int ti = 0; ti < 2; ti++) {
        int r0 = rn + ti * 16 + (lane >> 2);
        red[r0 * 8 + wm * 4 + (lane & 3)]       = rsA[ti];
        red[(r0 + 8) * 8 + wm * 4 + (lane & 3)] = rsB[ti];
    }
    if (offd && lane < 4) {
#pragma unroll
        for (int tj = 0; tj < 8; tj++) {
            redT[wn * 128 + cm + tj * 8 + 2 * lane]     = colp0[tj];
            redT[wn * 128 + cm + tj * 8 + 2 * lane + 1] = colp1[tj];
        }
    }
    // transpose stage half 0 (warps wn 0,1 hold rows 0..63)
    unsigned* stage = (unsigned*)(smc + K2_STG);
    if (offd && wn < 2) {
#pragma unroll
        for (int ti = 0; ti < 2; ti++) {
            int r0 = rn + ti * 16 + (lane >> 2);
#pragma unroll
            for (int tj = 0; tj < 8; tj++) {
                int c0 = cm + tj * 8 + 2 * (lane & 3);
                float p0 = c[ti][tj][0], p1 = c[ti][tj][1], p2 = c[ti][tj][2], p3 = c[ti][tj][3];
                __nv_bfloat16 h0 = __float2bfloat16(p0), h1 = __float2bfloat16(p1);
                __nv_bfloat16 h2 = __float2bfloat16(p2), h3 = __float2bfloat16(p3);
                stage[r0 * 129 + c0]           = packbf(h0, __float2bfloat16(p0 - __bfloat162float(h0)));
                stage[r0 * 129 + c0 + 1]       = packbf(h1, __float2bfloat16(p1 - __bfloat162float(h1)));
                stage[(r0 + 8) * 129 + c0]     = packbf(h2, __float2bfloat16(p2 - __bfloat162float(h2)));
                stage[(r0 + 8) * 129 + c0 + 1] = packbf(h3, __float2bfloat16(p3 - __bfloat162float(h3)));
            }
        }
    }
    __syncthreads();
    if (tid < 128) {
        float s = 0.f;
#pragma unroll
        for (int j = 0; j < 8; j++) s += red[tid * 8 + j];
        g_rspart[((size_t)(b * 32 + nt) * 32 + mt) * 128 + tid] = s;
        if (offd) {
            float st = redT[tid] + redT[128 + tid] + redT[256 + tid] + redT[384 + tid];
            g_rspart[((size_t)(b * 32 + mt) * 32 + nt) * 128 + tid] = st;
        }
    }
    if (!offd) return;

    // transposed write-out (2 halves, 64 rows each)
#pragma unroll 1
    for (int h = 0; h < 2; h++) {
        if (h == 1) {
            __syncthreads();
            if (wn >= 2) {
#pragma unroll
                for (int ti = 0; ti < 2; ti++) {
                    int r0 = rn - 64 + ti * 16 + (lane >> 2);
#pragma unroll
                    for (int tj = 0; tj < 8; tj++) {
                        int c0 = cm + tj * 8 + 2 * (lane & 3);
                        float p0 = c[ti][tj][0], p1 = c[ti][tj][1], p2 = c[ti][tj][2], p3 = c[ti][tj][3];
                        __nv_bfloat16 h0 = __float2bfloat16(p0), h1 = __float2bfloat16(p1);
                        __nv_bfloat16 h2 = __float2bfloat16(p2), h3 = __float2bfloat16(p3);
                        stage[r0 * 129 + c0]           = packbf(h0, __float2bfloat16(p0 - __bfloat162float(h0)));
                        stage[r0 * 129 + c0 + 1]       = packbf(h1, __float2bfloat16(p1 - __bfloat162float(h1)));
                        stage[(r0 + 8) * 129 + c0]     = packbf(h2, __float2bfloat16(p2 - __bfloat162float(h2)));
                        stage[(r0 + 8) * 129 + c0 + 1] = packbf(h3, __float2bfloat16(p3 - __bfloat162float(h3)));
                    }
                }
            }
        }
        __syncthreads();
#pragma unroll 2
        for (int i = 0; i < 16; i++) {
            int cc = wid * 16 + i;
            unsigned u0 = stage[(2 * lane) * 129 + cc];
            unsigned u1 = stage[(2 * lane + 1) * 129 + cc];
            size_t off = (size_t)(b * N_ + mt * 128 + cc) * N_ + nt * 128 + h * 64 + 2 * lane;
            *(unsigned*)(g_ph + off) = (u0 & 0xFFFFu) | (u1 << 16);
            *(unsigned*)(g_pl + off) = (u0 >> 16) | (u1 & 0xFFFF0000u);
        }
    }
}

// ================= K2.6: reduce rowsums -> invs (fp32 + bf16 hi/lo) =================
__global__ void k_rowred()
{
    int idx = blockIdx.x * 256 + threadIdx.x;    // (b,n)
    int b = idx >> 12, n = idx & 4095;
    float s = 0.f;
    const float* p = g_rspart + ((size_t)(b * 32 + (n >> 7)) * 32) * 128 + (n & 127);
#pragma unroll
    for (int mt = 0; mt < 32; mt++) s += p[mt * 128];
    float inv = 1.0f / s;
    g_invs[idx] = inv;
    __nv_bfloat16 h = __float2bfloat16(inv);
    __nv_bfloat16 l = __float2bfloat16(inv - __bfloat162float(h));
    g_invsbf[(b * 2 + 0) * N_ + n] = h;
    g_invsbf[(b * 2 + 1) * N_ + n] = l;
}

// ================= K2.7: Av = v * invs, split hi/lo bf16 =================
__global__ void k_avbuild()
{
    int idx = blockIdx.x * 256 + threadIdx.x;    // 8*64*4096
    int b = idx >> 18, o = (idx >> 12) & 63, n = idx & 4095;
    float a = g_v[(size_t)(b * 64 + o) * N_ + n] * g_invs[b * N_ + n];
    __nv_bfloat16 h = __float2bfloat16(a);
    __nv_bfloat16 l = __float2bfloat16(a - __bfloat162float(h));
    g_av[(size_t)(b * 128 + o) * N_ + n]      = h;
    g_av[(size_t)(b * 128 + 64 + o) * N_ + n] = l;
}

// ================= K3: D = Av@(Ph+Pl), colsum via MMA, 3-stage cp.async; fused epilogue ===
// grid (16, 8), 256 thr; each block handles 2 mt tiles of 128 cols.
#define K3_WT    0           // 16384
#define K3_CS2   16384       // [4][128] f32 = 2048
#define K3_CS    18432       // [128] f32 = 512
#define K3_RED   18944       // 2048
#define K3_STG   21504
#define K3_SSZ   57600       // A 18432 | H 18432 | L 18432 | INV 2304
#define K3_SMEM  (21504 + 3*57600)   // 194304
__device__ __forceinline__ void k3_issue(unsigned sb, int st, int b, int mta, int nb, int tid)
{
    unsigned s0 = sb + K3_STG + st * K3_SSZ;
    const __nv_bfloat16* asrc = g_av + (size_t)b * 128 * N_ + nb;
    const __nv_bfloat16* hsrc = g_ph + ((size_t)(b * N_ + mta * 128)) * N_ + nb;
    const __nv_bfloat16* lsrc = g_pl + ((size_t)(b * N_ + mta * 128)) * N_ + nb;
    for (int i = tid; i < 1024; i += 256) {
        int row = i >> 3, cc = i & 7;
        unsigned doff = row * 144 + cc * 16;
        size_t soff = (size_t)row * N_ + cc * 8;
        cp16(s0 + doff,         asrc + soff);
        cp16(s0 + 18432 + doff, hsrc + soff);
        cp16(s0 + 36864 + doff, lsrc + soff);
    }
    if (tid < 16) {
        int row = tid >> 3, cc = tid & 7;
        cp16(s0 + 55296 + row * 144 + cc * 16,
             g_invsbf + (size_t)(b * 2 + row) * N_ + nb + cc * 8);
    }
}

__global__ void __launch_bounds__(256)
k_attn(const float* __restrict__ w_t, const float* __restrict__ b_t)
{
    extern __shared__ char smc[];
    unsigned sb = smem_u32(smc);
    int b = blockIdx.y;
    int tid = threadIdx.x, wid = tid >> 5, lane = tid & 31;
    float* Wts = (float*)(smc + K3_WT);
    float* cs2 = (float*)(smc + K3_CS2);
    float* cs  = (float*)(smc + K3_CS);

    for (int i = tid; i < 4096; i += 256) Wts[i] = w_t[i];
    // zero rows 2-15 of INV strips (all 3 stages) once
    for (int st = 0; st < 3; st++)
        for (int i = tid; i < 504; i += 256)   // 2016 bytes / 4
            *(unsigned*)(smc + K3_STG + st * K3_SSZ + 55296 + 288 + i * 4) = 0;

    int wn = wid >> 1, wm = wid & 1;
    int rn = wn * 32, cm = wm * 64;

#pragma unroll 1
    for (int half = 0; half < 2; half++) {
        int mta = blockIdx.x * 2 + half;
        float c[2][8][4], ccs[8][4];
#pragma unroll
        for (int tj = 0; tj < 8; tj++) {
#pragma unroll
            for (int q = 0; q < 4; q++) { c[0][tj][q] = 0.f; c[1][tj][q] = 0.f; ccs[tj][q] = 0.f; }
        }
        __syncthreads();                      // Ds/prev reads done before stage overwrite
        k3_issue(sb, 0, b, mta, 0, tid); CP_COMMIT();
        k3_issue(sb, 1, b, mta, 64, tid); CP_COMMIT();

        for (int ch = 0; ch < 64; ch++) {
            if (ch + 2 < 64) CP_WAIT(1); else CP_WAIT(0);
            __syncthreads();
            if (ch + 2 < 64) { k3_issue(sb, (ch + 2) % 3, b, mta, (ch + 2) * 64, tid); CP_COMMIT(); }

            unsigned sA = sb + K3_STG + (ch % 3) * K3_SSZ;
            unsigned sH = sA + 18432, sL = sA + 36864, sI = sA + 55296;
#pragma unroll
            for (int ks = 0; ks < 4; ks++) {
                unsigned a[2][4], ainv[4];
                ldsm_x4(a[0], sA + (rn + (lane & 15)) * 144 + ks * 32 + (lane >> 4) * 16);
                ldsm_x4(a[1], sA + (rn + 16 + (lane & 15)) * 144 + ks * 32 + (lane >> 4) * 16);
                bool mine = (ks == wn);
                if (mine) ldsm_x4(ainv, sI + (lane & 15) * 144 + ks * 32 + (lane >> 4) * 16);
#pragma unroll
                for (int tj = 0; tj < 8; tj++) {
                    unsigned bb[4];     // bh in [0,1], bl in [2,3]
                    unsigned boff = (cm + tj * 8 + (lane & 7)) * 144 + ks * 32 + ((lane >> 3) & 1) * 16;
                    ldsm_x4(bb, ((lane >> 4) ? sL : sH) + boff);
                    mma16816(c[0][tj], a[0], bb);     mma16816(c[1][tj], a[1], bb);
                    mma16816(c[0][tj], a[0], bb + 2); mma16816(c[1][tj], a[1], bb + 2);
                    if (mine) { mma16816(ccs[tj], ainv, bb); mma16816(ccs[tj], ainv, bb + 2); }
                }
            }
        }
        // colsum reduce: rows 0(hi),1(lo) of ccs live on lanes 0-7
#pragma unroll
        for (int tj = 0; tj < 8; tj++) {
            float v0 = ccs[tj][0] + __shfl_xor_sync(0xffffffff, ccs[tj][0], 4);
            float v1 = ccs[tj][1] + __shfl_xor_sync(0xffffffff, ccs[tj][1], 4);
            if (lane < 4) {
                cs2[wn * 128 + cm + tj * 8 + 2 * lane]     = v0;
                cs2[wn * 128 + cm + tj * 8 + 2 * lane + 1] = v1;
            }
        }
        __syncthreads();
        if (tid < 128)
            cs[tid] = cs2[tid] + cs2[128 + tid] + cs2[256 + tid] + cs2[384 + tid];
        __syncthreads();

        // frags -> Ds smem [128][132] (reuses stage area; all cp groups drained)
        float* Ds = (float*)(smc + K3_STG);
#pragma unroll
        for (int ti = 0; ti < 2; ti++) {
            int r0 = rn + ti * 16 + (lane >> 2);
#pragma unroll
            for (int tj = 0; tj < 8; tj++) {
                int c0 = cm + tj * 8 + 2 * (lane & 3);
                *(float2*)&Ds[r0 * 132 + c0]       = make_float2(c[ti][tj][0], c[ti][tj][1]);
                *(float2*)&Ds[(r0 + 8) * 132 + c0] = make_float2(c[ti][tj][2], c[ti][tj][3]);
            }
        }
        __syncthreads();

        int o = tid >> 2, g = tid & 3;
        {   // d = x_c - (D[o]+D[o+64])/(1e-9+cs)
            const float* xcb = g_xc + (size_t)(b * 64 + o) * N_ + mta * 128;
#pragma unroll 4
            for (int k = 0; k < 32; k++) {
                int m = g * 32 + k;
                float xru = Ds[o * 132 + m] + Ds[(o + 64) * 132 + m];
                Ds[o * 132 + m] = xcb[m] - xru / (1e-9f + cs[m]);
            }
        }
        __syncthreads();

        {   // t = Wt @ d + b_t ; BN partials
            float bias = b_t[o];
            float psum = 0.f, psq = 0.f;
            float* tout = g_t + (size_t)(b * 64 + o) * N_ + mta * 128;
#pragma unroll
            for (int rep = 0; rep < 2; rep++) {
                int m0 = g * 32 + rep * 16;
                float acc[16];
#pragma unroll
                for (int j = 0; j < 16; j++) acc[j] = 0.f;
#pragma unroll 4
                for (int k = 0; k < 64; k++) {
                    float w = Wts[o * 64 + k];
                    const float4* dr = (const float4*)&Ds[k * 132 + m0];
#pragma unroll
                    for (int q = 0; q < 4; q++) {
                        float4 d4 = dr[q];
                        acc[4*q]   += w * d4.x; acc[4*q+1] += w * d4.y;
                        acc[4*q+2] += w * d4.z; acc[4*q+3] += w * d4.w;
                    }
                }
#pragma unroll
                for (int j = 0; j < 16; j += 4) {
                    float t0 = acc[j] + bias, t1 = acc[j+1] + bias, t2 = acc[j+2] + bias, t3 = acc[j+3] + bias;
                    *(float4*)&tout[m0 + j] = make_float4(t0, t1, t2, t3);
                    psum += t0 + t1 + t2 + t3;
                    psq  += t0*t0 + t1*t1 + t2*t2 + t3*t3;
                }
            }
            float* Rs = (float*)(smc + K3_RED);
            float* Rq = Rs + 256;
            Rs[o * 4 + g] = psum;
            Rq[o * 4 + g] = psq;
            __syncthreads();
            if (tid < 64) {
                float s = Rs[tid*4] + Rs[tid*4+1] + Rs[tid*4+2] + Rs[tid*4+3];
                float q = Rq[tid*4] + Rq[tid*4+1] + Rq[tid*4+2] + Rq[tid*4+3];
                int blk = b * 32 + mta;
                g_part[tid * 256 + blk]            = s;
                g_part[64 * 256 + tid * 256 + blk] = q;
            }
        }
    }
}

// ================= K5: BN stats =================
__global__ void k_bnstats(const float* __restrict__ gamma, const float* __restrict__ beta)
{
    int c = threadIdx.x;
    if (c >= 64) return;
    float s = 0.f, q = 0.f;
    for (int j = 0; j < 256; j++) {
        s += g_part[c * 256 + j];
        q += g_part[64 * 256 + c * 256 + j];
    }
    const float invN = 1.0f / 32768.0f;
    float mean = s * invN;
    float var  = q * invN - mean * mean;
    float sc = gamma[c] * rsqrtf(var + 1e-5f);
    g_bn[c]      = sc;
    g_bn[64 + c] = beta[c] - mean * sc;
}

// ================= K6: out = x_c + relu(scale*t + shift) =================
__global__ void k_final(float* __restrict__ out)
{
    int i4 = blockIdx.x * 256 + threadIdx.x;
    if (i4 >= B_ * C2_ * (N_ / 4)) return;
    int ch = (i4 >> 10) & 63;
    float sc = g_bn[ch], sh = g_bn[64 + ch];
    float4 t  = ((const float4*)g_t)[i4];
    float4 xc = ((const float4*)g_xc)[i4];
    float4 r;
    r.x = xc.x + fmaxf(0.f, sc * t.x + sh);
    r.y = xc.y + fmaxf(0.f, sc * t.y + sh);
    r.z = xc.z + fmaxf(0.f, sc * t.z + sh);
    r.w = xc.w + fmaxf(0.f, sc * t.w + sh);
    ((float4*)out)[i4] = r;
}

// ================= launch =================
extern "C" void kernel_launch(void* const* d_in, const int* in_sizes, int n_in,
                              void* d_out, int out_size)
{
    const float* x     = (const float*)d_in[0];
    const float* w_qk  = (const float*)d_in[1];
    const float* w_v   = (const float*)d_in[2];
    const float* b_v   = (const float*)d_in[3];
    const float* w_x   = (const float*)d_in[4];
    const float* w_t   = (const float*)d_in[5];
    const float* b_t   = (const float*)d_in[6];
    const float* gamma = (const float*)d_in[7];
    const float* beta  = (const float*)d_in[8];
    float* out = (float*)d_out;

    cudaFuncSetAttribute(k_proj,   cudaFuncAttributeMaxDynamicSharedMemorySize, 98304);
    cudaFuncSetAttribute(k_energy, cudaFuncAttributeMaxDynamicSharedMemorySize, K2_SMEM);
    cudaFuncSetAttribute(k_attn,   cudaFuncAttributeMaxDynamicSharedMemorySize, K3_SMEM);

    k_proj    <<<dim3(64, 8), 256, 98304>>>(x, w_qk, w_v, b_v, w_x);
    k_energy  <<<dim3(528, 8), 256, K2_SMEM>>>();
    k_rowred  <<<128, 256>>>();
    k_avbuild <<<8192, 256>>>();
    k_attn    <<<dim3(16, 8), 256, K3_SMEM>>>(w_t, b_t);
    k_bnstats <<<1, 64>>>(gamma, beta);
    k_final   <<<2048, 256>>>(out);
}

// round 9
// speedup vs baseline: 5.0776x; 1.0293x over previous
#include <cuda_runtime.h>
#include <cuda_bf16.h>
#include <math.h>

#define B_  8
#define C_  128
#define N_  4096
#define C2_ 64

// ---------------- scratch ----------------
__device__ __align__(16) __nv_bfloat16 g_qs[B_*N_*128];    // [b][n][k] k:0-63 hi, 64-127 lo
__device__ __align__(16) float g_v [B_*C2_*N_];
__device__ __align__(16) float g_xc[B_*C2_*N_];
__device__ __align__(16) float g_rspart[B_*32*32*128];     // rowsum partials (b,nt,mt,row)
__device__ __align__(16) __nv_bfloat16 g_invsbf[B_*2*N_];  // [b][hi/lo][n]
__device__ __align__(16) __nv_bfloat16 g_av[B_*128*N_];    // [b][r][n] r:0-63 hi(v*invs), 64-127 lo
__device__ __align__(16) float g_t [B_*C2_*N_];
__device__ __align__(16) float g_part[2*64*256];
__device__ __align__(16) float g_bn[128];
__device__ __align__(16) __nv_bfloat16 g_ph[(size_t)B_*N_*N_];  // hi plane of exp(E), UPPER tiles only
__device__ __align__(16) __nv_bfloat16 g_pl[(size_t)B_*N_*N_];  // lo plane, UPPER tiles only

// ---------------- helpers ----------------
__device__ __forceinline__ unsigned smem_u32(const void* p){
    unsigned a; asm("{ .reg .u64 t; cvta.to.shared.u64 t, %1; cvt.u32.u64 %0, t; }" : "=r"(a) : "l"(p)); return a;
}
__device__ __forceinline__ void ldsm_x4(unsigned* r, unsigned addr){
    asm volatile("ldmatrix.sync.aligned.m8n8.x4.shared.b16 {%0,%1,%2,%3}, [%4];"
        : "=r"(r[0]), "=r"(r[1]), "=r"(r[2]), "=r"(r[3]) : "r"(addr));
}
__device__ __forceinline__ void ldsm_x4_t(unsigned* r, unsigned addr){
    asm volatile("ldmatrix.sync.aligned.m8n8.x4.trans.shared.b16 {%0,%1,%2,%3}, [%4];"
        : "=r"(r[0]), "=r"(r[1]), "=r"(r[2]), "=r"(r[3]) : "r"(addr));
}
__device__ __forceinline__ void mma16816(float* c, const unsigned* a, const unsigned* b){
    asm volatile("mma.sync.aligned.m16n8k16.row.col.f32.bf16.bf16.f32 "
        "{%0,%1,%2,%3}, {%4,%5,%6,%7}, {%8,%9}, {%0,%1,%2,%3};"
        : "+f"(c[0]), "+f"(c[1]), "+f"(c[2]), "+f"(c[3])
        : "r"(a[0]), "r"(a[1]), "r"(a[2]), "r"(a[3]), "r"(b[0]), "r"(b[1]));
}
__device__ __forceinline__ void cp16(unsigned s, const void* g){
    asm volatile("{ .reg .u64 gp; cvta.to.global.u64 gp, %1; cp.async.cg.shared.global [%0], [gp], 16; }"
        :: "r"(s), "l"(g));
}
#define CP_COMMIT() asm volatile("cp.async.commit_group;" ::: "memory")
#define CP_WAIT(n)  asm volatile("cp.async.wait_group %0;" :: "n"(n) : "memory")

__device__ __forceinline__ unsigned packbf(__nv_bfloat16 a, __nv_bfloat16 b){
    return (unsigned)__bfloat16_as_ushort(a) | ((unsigned)__bfloat16_as_ushort(b) << 16);
}

// ================= K1: projections via split-bf16 HMMA =================
// grid (nt=32, b=8), 256 thr. M=192 rows (qk|v|xc), N=128 cols, K=128, 3 passes.
#define P_WH 0
#define P_WL 52224
#define P_XH 104448
#define P_XL 139264
#define P_SMEM 174080
__global__ void __launch_bounds__(256)
k_proj(const float* __restrict__ x, const float* __restrict__ w_qk,
       const float* __restrict__ w_v, const float* __restrict__ b_v,
       const float* __restrict__ w_x)
{
    extern __shared__ char smc[];
    unsigned sb = smem_u32(smc);
    int b = blockIdx.y, nt = blockIdx.x;
    int tid = threadIdx.x, wid = tid >> 5, lane = tid & 31;

    // stage split weights: rows 0-63 qk, 64-127 v, 128-191 x ; [192][136] halves
    unsigned short* WH = (unsigned short*)(smc + P_WH);
    unsigned short* WL = (unsigned short*)(smc + P_WL);
    for (int i = tid; i < 24576; i += 256) {
        float wv = (i < 8192) ? w_qk[i] : (i < 16384 ? w_v[i - 8192] : w_x[i - 16384]);
        int row = i >> 7, cc = i & 127;
        __nv_bfloat16 h = __float2bfloat16(wv);
        __nv_bfloat16 l = __float2bfloat16(wv - __bfloat162float(h));
        WH[row * 136 + cc] = __bfloat16_as_ushort(h);
        WL[row * 136 + cc] = __bfloat16_as_ushort(l);
    }
    // stage split x tile: [c=128][n=128] halves (k-major rows for ldsm-trans B)
    unsigned short* XH = (unsigned short*)(smc + P_XH);
    unsigned short* XL = (unsigned short*)(smc + P_XL);
    const float* xp = x + (size_t)(b * C_) * N_ + nt * 128;
    for (int i = tid; i < 16384; i += 256) {
        int c = i >> 7, n = i & 127;
        float v = xp[(size_t)c * N_ + n];
        __nv_bfloat16 h = __float2bfloat16(v);
        __nv_bfloat16 l = __float2bfloat16(v - __bfloat162float(h));
        XH[c * 136 + n] = __bfloat16_as_ushort(h);
        XL[c * 136 + n] = __bfloat16_as_ushort(l);
    }
    __syncthreads();

    int wn = wid >> 1, wm = wid & 1;      // wn rows 48 each, wm cols 64
    int rm = wn * 48, cn = wm * 64;
    float c[3][8][4];
#pragma unroll
    for (int ti = 0; ti < 3; ti++)
#pragma unroll
        for (int tj = 0; tj < 8; tj++)
#pragma unroll
            for (int q = 0; q < 4; q++) c[ti][tj][q] = 0.f;

#pragma unroll
    for (int p = 0; p < 3; p++) {
        unsigned wa = sb + ((p == 2) ? P_WL : P_WH);
        unsigned xb = sb + ((p == 1) ? P_XL : P_XH);
#pragma unroll
        for (int ks = 0; ks < 8; ks++) {
            unsigned a[3][4];
#pragma unroll
            for (int ti = 0; ti < 3; ti++)
                ldsm_x4(a[ti], wa + (rm + ti * 16 + (lane & 15)) * 272 + ks * 32 + (lane >> 4) * 16);
#pragma unroll
            for (int tjp = 0; tjp < 4; tjp++) {
                unsigned bb[4];
                ldsm_x4_t(bb, xb + (ks * 16 + (lane & 15)) * 272
                              + (cn + tjp * 16 + ((lane >> 4) << 3)) * 2);
#pragma unroll
                for (int ti = 0; ti < 3; ti++) {
                    mma16816(c[ti][2 * tjp],     a[ti], bb);
                    mma16816(c[ti][2 * tjp + 1], a[ti], bb + 2);
                }
            }
        }
    }
    __syncthreads();   // XH/XL dead; reuse XH region as qk stage

    unsigned short* qstage = (unsigned short*)(smc + P_XH);  // [128 n][128 k: 0-63 hi | 64-127 lo]
#pragma unroll
    for (int ti = 0; ti < 3; ti++) {
        int r0 = rm + ti * 16;
        int r = r0 + (lane >> 2);
#pragma unroll
        for (int tj = 0; tj < 8; tj++) {
            int c0 = cn + tj * 8 + 2 * (lane & 3);
            float v0 = c[ti][tj][0], v1 = c[ti][tj][1], v2 = c[ti][tj][2], v3 = c[ti][tj][3];
            if (r0 < 64) {
                __nv_bfloat16 h0 = __float2bfloat16(v0), h1 = __float2bfloat16(v1);
                __nv_bfloat16 h2 = __float2bfloat16(v2), h3 = __float2bfloat16(v3);
                qstage[c0 * 128 + r]            = __bfloat16_as_ushort(h0);
                qstage[c0 * 128 + 64 + r]       = __bfloat16_as_ushort(__float2bfloat16(v0 - __bfloat162float(h0)));
                qstage[(c0 + 1) * 128 + r]      = __bfloat16_as_ushort(h1);
                qstage[(c0 + 1) * 128 + 64 + r] = __bfloat16_as_ushort(__float2bfloat16(v1 - __bfloat162float(h1)));
                qstage[c0 * 128 + r + 8]            = __bfloat16_as_ushort(h2);
                qstage[c0 * 128 + 64 + r + 8]       = __bfloat16_as_ushort(__float2bfloat16(v2 - __bfloat162float(h2)));
                qstage[(c0 + 1) * 128 + r + 8]      = __bfloat16_as_ushort(h3);
                qstage[(c0 + 1) * 128 + 64 + r + 8] = __bfloat16_as_ushort(__float2bfloat16(v3 - __bfloat162float(h3)));
            } else if (r0 < 128) {
                float ba = b_v[r - 64], bb2 = b_v[r - 56];
                *(float2*)&g_v[(size_t)(b * 64 + r - 64) * N_ + nt * 128 + c0] = make_float2(v0 + ba, v1 + ba);
                *(float2*)&g_v[(size_t)(b * 64 + r - 56) * N_ + nt * 128 + c0] = make_float2(v2 + bb2, v3 + bb2);
            } else {
                *(float2*)&g_xc[(size_t)(b * 64 + r - 128) * N_ + nt * 128 + c0] = make_float2(v0, v1);
                *(float2*)&g_xc[(size_t)(b * 64 + r - 120) * N_ + nt * 128 + c0] = make_float2(v2, v3);
            }
        }
    }
    __syncthreads();
    for (int i = tid; i < 2048; i += 256) {
        int row = i >> 4, cc = i & 15;
        ((uint4*)(g_qs + (size_t)(b * N_ + nt * 128 + row) * 128))[cc] =
            ((const uint4*)(qstage + row * 128))[cc];
    }
}

// ================= K2: symmetric E=Q^T Q, P=exp(E) upper tiles only, rowsums both sides ===
// grid (528 upper-tri tiles, 8), 256 thr, 2 CTA/SM. Tile 128(n) x 128(m), mt >= nt.
#define K2_AS 0
#define K2_BS 34816
#define K2_RED 0            // [128][8] f32 overlay after MMA
#define K2_RDT 4096         // [4][128] f32
#define K2_SMEM 69632
__global__ void __launch_bounds__(256, 2)
k_energy()
{
    extern __shared__ char smc[];
    unsigned sb = smem_u32(smc);
    int b = blockIdx.y;
    int tid = threadIdx.x, wid = tid >> 5, lane = tid & 31;

    int u = blockIdx.x, nt = 0;
    while (u >= 32 - nt) { u -= 32 - nt; nt++; }
    int mt = nt + u;

    {
        const uint4* asrc = (const uint4*)(g_qs + (size_t)(b * N_ + nt * 128) * 128);
        const uint4* bsrc = (const uint4*)(g_qs + (size_t)(b * N_ + mt * 128) * 128);
        for (int i = tid; i < 2048; i += 256) {
            int row = i >> 4, cc = i & 15;
            *(uint4*)(smc + K2_AS + row * 272 + cc * 16) = asrc[i];
            *(uint4*)(smc + K2_BS + row * 272 + cc * 16) = bsrc[i];
        }
    }
    __syncthreads();

    int wn = wid >> 1, wm = wid & 1;
    int rn = wn * 32, cm = wm * 64;
    float c[2][8][4];
#pragma unroll
    for (int ti = 0; ti < 2; ti++)
#pragma unroll
        for (int tj = 0; tj < 8; tj++)
#pragma unroll
            for (int q = 0; q < 4; q++) c[ti][tj][q] = 0.f;

    const int qa[3] = {0, 0, 1}, qb[3] = {0, 1, 0};
#pragma unroll
    for (int s = 0; s < 12; s++) {
        int grp = s >> 2, km = (s & 3) * 32;
        int ka = qa[grp] * 128 + km, kb = qb[grp] * 128 + km;
        unsigned a[2][4];
#pragma unroll
        for (int ti = 0; ti < 2; ti++)
            ldsm_x4(a[ti], sb + K2_AS + (rn + ti * 16 + (lane & 15)) * 272 + ka + (lane >> 4) * 16);
#pragma unroll
        for (int tjp = 0; tjp < 4; tjp++) {
            unsigned bb[4];
            ldsm_x4(bb, sb + K2_BS + (cm + tjp * 16 + ((lane >> 4) << 3) + (lane & 7)) * 272
                        + kb + ((lane >> 3) & 1) * 16);
            mma16816(c[0][2*tjp],   a[0], bb);     mma16816(c[1][2*tjp],   a[1], bb);
            mma16816(c[0][2*tjp+1], a[0], bb + 2); mma16816(c[1][2*tjp+1], a[1], bb + 2);
        }
    }

    // epilogue: exp, split, direct stores (upper tile only), rowsums both orientations
    bool offd = (mt != nt);
    float rsA[2] = {0.f, 0.f}, rsB[2] = {0.f, 0.f};
    float colp0[8], colp1[8];
#pragma unroll
    for (int tj = 0; tj < 8; tj++) { colp0[tj] = 0.f; colp1[tj] = 0.f; }
    size_t prow = (size_t)(b * N_ + nt * 128) * N_ + mt * 128;
#pragma unroll
    for (int ti = 0; ti < 2; ti++) {
        int r0 = rn + ti * 16 + (lane >> 2);
#pragma unroll
        for (int tj = 0; tj < 8; tj++) {
            int c0 = cm + tj * 8 + 2 * (lane & 3);
            float p0 = __expf(c[ti][tj][0]), p1 = __expf(c[ti][tj][1]);
            float p2 = __expf(c[ti][tj][2]), p3 = __expf(c[ti][tj][3]);
            rsA[ti] += p0 + p1;  rsB[ti] += p2 + p3;
            colp0[tj] += p0 + p2; colp1[tj] += p1 + p3;
            __nv_bfloat16 h0 = __float2bfloat16(p0), h1 = __float2bfloat16(p1);
            __nv_bfloat16 h2 = __float2bfloat16(p2), h3 = __float2bfloat16(p3);
            __nv_bfloat16 l0 = __float2bfloat16(p0 - __bfloat162float(h0));
            __nv_bfloat16 l1 = __float2bfloat16(p1 - __bfloat162float(h1));
            __nv_bfloat16 l2 = __float2bfloat16(p2 - __bfloat162float(h2));
            __nv_bfloat16 l3 = __float2bfloat16(p3 - __bfloat162float(h3));
            size_t ba = prow + (size_t)r0 * N_ + c0;
            size_t bc = ba + (size_t)8 * N_;
            *(unsigned*)(g_ph + ba) = packbf(h0, h1);
            *(unsigned*)(g_pl + ba) = packbf(l0, l1);
            *(unsigned*)(g_ph + bc) = packbf(h2, h3);
            *(unsigned*)(g_pl + bc) = packbf(l2, l3);
        }
    }
    if (offd) {
#pragma unroll
        for (int tj = 0; tj < 8; tj++) {
            colp0[tj] += __shfl_xor_sync(0xffffffff, colp0[tj], 4);
            colp0[tj] += __shfl_xor_sync(0xffffffff, colp0[tj], 8);
            colp0[tj] += __shfl_xor_sync(0xffffffff, colp0[tj], 16);
            colp1[tj] += __shfl_xor_sync(0xffffffff, colp1[tj], 4);
            colp1[tj] += __shfl_xor_sync(0xffffffff, colp1[tj], 8);
            colp1[tj] += __shfl_xor_sync(0xffffffff, colp1[tj], 16);
        }
    }
    __syncthreads();   // As/Bs dead

    float* red  = (float*)(smc + K2_RED);
    float* redT = (float*)(smc + K2_RDT);
#pragma unroll
    for (int ti = 0; ti < 2; ti++) {
        int r0 = rn + ti * 16 + (lane >> 2);
        red[r0 * 8 + wm * 4 + (lane & 3)]       = rsA[ti];
        red[(r0 + 8) * 8 + wm * 4 + (lane & 3)] = rsB[ti];
    }
    if (offd && lane < 4) {
#pragma unroll
        for (int tj = 0; tj < 8; tj++) {
            redT[wn * 128 + cm + tj * 8 + 2 * lane]     = colp0[tj];
            redT[wn * 128 + cm + tj * 8 + 2 * lane + 1] = colp1[tj];
        }
    }
    __syncthreads();
    if (tid < 128) {
        float s = 0.f;
#pragma unroll
        for (int j = 0; j < 8; j++) s += red[tid * 8 + j];
        g_rspart[((size_t)(b * 32 + nt) * 32 + mt) * 128 + tid] = s;
        if (offd) {
            float st = redT[tid] + redT[128 + tid] + redT[256 + tid] + redT[384 + tid];
            g_rspart[((size_t)(b * 32 + mt) * 32 + nt) * 128 + tid] = st;
        }
    }
}

// ================= K2.5: rowsum reduce -> invsbf, Av = v*inv split (merged) =================
__global__ void k_rowav()
{
    int idx = blockIdx.x * 256 + threadIdx.x;    // (b,n) over 32768
    int b = idx >> 12, n = idx & 4095;
    float s = 0.f;
    const float* p = g_rspart + ((size_t)(b * 32 + (n >> 7)) * 32) * 128 + (n & 127);
#pragma unroll
    for (int mt = 0; mt < 32; mt++) s += p[mt * 128];
    float inv = 1.0f / s;
    __nv_bfloat16 ih = __float2bfloat16(inv);
    g_invsbf[(b * 2 + 0) * N_ + n] = ih;
    g_invsbf[(b * 2 + 1) * N_ + n] = __float2bfloat16(inv - __bfloat162float(ih));
    const float* vs = g_v + (size_t)(b * 64) * N_ + n;
    __nv_bfloat16* avh = g_av + (size_t)(b * 128) * N_ + n;
#pragma unroll 4
    for (int o = 0; o < 64; o++) {
        float a = vs[(size_t)o * N_] * inv;
        __nv_bfloat16 h = __float2bfloat16(a);
        avh[(size_t)o * N_]        = h;
        avh[(size_t)(o + 64) * N_] = __float2bfloat16(a - __bfloat162float(h));
    }
}

// ================= K3: D = Av@(Ph+Pl), symmetric reads (direct/trans), colsum via MMA ===
// grid (16, 8), 256 thr; each block: 2 mt tiles of 128 cols, K=4096 x 2 planes.
#define K3_WT    0           // 16384
#define K3_CS2   16384       // [4][128] f32
#define K3_CS    18432       // [128] f32
#define K3_RED   18944       // 2048
#define K3_STG   21504
#define K3_SSZ   57600       // A 18432 | H 18432 | L 18432 | INV 2304
#define K3_SMEM  (21504 + 3*57600)
__device__ __forceinline__ void k3_issue(unsigned sb, int st, int b, int mta, int ch, int tid)
{
    unsigned s0 = sb + K3_STG + st * K3_SSZ;
    int nb = ch << 6;
    bool tr = (mta > (ch >> 1));
    const __nv_bfloat16* asrc = g_av + (size_t)b * 128 * N_ + nb;
    const __nv_bfloat16 *hsrc, *lsrc;
    if (!tr) {      // direct: storage rows m (mta tile), cols n-chunk
        hsrc = g_ph + ((size_t)(b * N_ + mta * 128)) * N_ + nb;
        lsrc = g_pl + ((size_t)(b * N_ + mta * 128)) * N_ + nb;
    } else {        // transposed: storage rows n-chunk, cols m (mta tile)
        hsrc = g_ph + ((size_t)(b * N_ + nb)) * N_ + mta * 128;
        lsrc = g_pl + ((size_t)(b * N_ + nb)) * N_ + mta * 128;
    }
    for (int i = tid; i < 1024; i += 256) {
        int ar = i >> 3, ac = i & 7;
        cp16(s0 + ar * 144 + ac * 16, asrc + (size_t)ar * N_ + ac * 8);
        if (!tr) {
            cp16(s0 + 18432 + ar * 144 + ac * 16, hsrc + (size_t)ar * N_ + ac * 8);
            cp16(s0 + 36864 + ar * 144 + ac * 16, lsrc + (size_t)ar * N_ + ac * 8);
        } else {
            int rr = i >> 4, cc = i & 15;
            cp16(s0 + 18432 + rr * 272 + cc * 16, hsrc + (size_t)rr * N_ + cc * 8);
            cp16(s0 + 36864 + rr * 272 + cc * 16, lsrc + (size_t)rr * N_ + cc * 8);
        }
    }
    if (tid < 16) {
        int row = tid >> 3, cc = tid & 7;
        cp16(s0 + 55296 + row * 144 + cc * 16,
             g_invsbf + (size_t)(b * 2 + row) * N_ + nb + cc * 8);
    }
}

__global__ void __launch_bounds__(256)
k_attn(const float* __restrict__ w_t, const float* __restrict__ b_t)
{
    extern __shared__ char smc[];
    unsigned sb = smem_u32(smc);
    int b = blockIdx.y;
    int tid = threadIdx.x, wid = tid >> 5, lane = tid & 31;
    float* Wts = (float*)(smc + K3_WT);
    float* cs2 = (float*)(smc + K3_CS2);
    float* cs  = (float*)(smc + K3_CS);

    for (int i = tid; i < 4096; i += 256) Wts[i] = w_t[i];
    for (int st = 0; st < 3; st++)
        for (int i = tid; i < 504; i += 256)
            *(unsigned*)(smc + K3_STG + st * K3_SSZ + 55296 + 288 + i * 4) = 0;

    int wn = wid >> 1, wm = wid & 1;
    int rn = wn * 32, cm = wm * 64;

#pragma unroll 1
    for (int half = 0; half < 2; half++) {
        int mta = blockIdx.x * 2 + half;
        float c[2][8][4], ccs[8][4];
#pragma unroll
        for (int tj = 0; tj < 8; tj++) {
#pragma unroll
            for (int q = 0; q < 4; q++) { c[0][tj][q] = 0.f; c[1][tj][q] = 0.f; ccs[tj][q] = 0.f; }
        }
        __syncthreads();
        k3_issue(sb, 0, b, mta, 0, tid); CP_COMMIT();
        k3_issue(sb, 1, b, mta, 1, tid); CP_COMMIT();

        for (int ch = 0; ch < 64; ch++) {
            if (ch + 2 < 64) CP_WAIT(1); else CP_WAIT(0);
            __syncthreads();
            if (ch + 2 < 64) { k3_issue(sb, (ch + 2) % 3, b, mta, ch + 2, tid); CP_COMMIT(); }

            unsigned sA = sb + K3_STG + (ch % 3) * K3_SSZ;
            unsigned sH = sA + 18432, sL = sA + 36864, sI = sA + 55296;
            bool tr = (mta > (ch >> 1));
            if (!tr) {
#pragma unroll
                for (int ks = 0; ks < 4; ks++) {
                    unsigned a[2][4], ainv[4];
                    ldsm_x4(a[0], sA + (rn + (lane & 15)) * 144 + ks * 32 + (lane >> 4) * 16);
                    ldsm_x4(a[1], sA + (rn + 16 + (lane & 15)) * 144 + ks * 32 + (lane >> 4) * 16);
                    bool mine = (ks == wn);
                    if (mine) ldsm_x4(ainv, sI + (lane & 15) * 144 + ks * 32 + (lane >> 4) * 16);
#pragma unroll
                    for (int tj = 0; tj < 8; tj++) {
                        unsigned bb[4];
                        unsigned boff = (cm + tj * 8 + (lane & 7)) * 144 + ks * 32 + ((lane >> 3) & 1) * 16;
                        ldsm_x4(bb, ((lane >> 4) ? sL : sH) + boff);
                        mma16816(c[0][tj], a[0], bb);     mma16816(c[1][tj], a[1], bb);
                        mma16816(c[0][tj], a[0], bb + 2); mma16816(c[1][tj], a[1], bb + 2);
                        if (mine) { mma16816(ccs[tj], ainv, bb); mma16816(ccs[tj], ainv, bb + 2); }
                    }
                }
            } else {
#pragma unroll
                for (int ks = 0; ks < 4; ks++) {
                    unsigned a[2][4], ainv[4];
                    ldsm_x4(a[0], sA + (rn + (lane & 15)) * 144 + ks * 32 + (lane >> 4) * 16);
                    ldsm_x4(a[1], sA + (rn + 16 + (lane & 15)) * 144 + ks * 32 + (lane >> 4) * 16);
                    bool mine = (ks == wn);
                    if (mine) ldsm_x4(ainv, sI + (lane & 15) * 144 + ks * 32 + (lane >> 4) * 16);
#pragma unroll
                    for (int tj = 0; tj < 8; tj++) {
                        unsigned bb[4];
                        unsigned boff = (ks * 16 + (lane & 15)) * 272 + (cm + tj * 8) * 2;
                        ldsm_x4_t(bb, ((lane >> 4) ? sL : sH) + boff);
                        mma16816(c[0][tj], a[0], bb);     mma16816(c[1][tj], a[1], bb);
                        mma16816(c[0][tj], a[0], bb + 2); mma16816(c[1][tj], a[1], bb + 2);
                        if (mine) { mma16816(ccs[tj], ainv, bb); mma16816(ccs[tj], ainv, bb + 2); }
                    }
                }
            }
        }
#pragma unroll
        for (int tj = 0; tj < 8; tj++) {
            float v0 = ccs[tj][0] + __shfl_xor_sync(0xffffffff, ccs[tj][0], 4);
            float v1 = ccs[tj][1] + __shfl_xor_sync(0xffffffff, ccs[tj][1], 4);
            if (lane < 4) {
                cs2[wn * 128 + cm + tj * 8 + 2 * lane]     = v0;
                cs2[wn * 128 + cm + tj * 8 + 2 * lane + 1] = v1;
            }
        }
        __syncthreads();
        if (tid < 128)
            cs[tid] = cs2[tid] + cs2[128 + tid] + cs2[256 + tid] + cs2[384 + tid];
        __syncthreads();

        float* Ds = (float*)(smc + K3_STG);
#pragma unroll
        for (int ti = 0; ti < 2; ti++) {
            int r0 = rn + ti * 16 + (lane >> 2);
#pragma unroll
            for (int tj = 0; tj < 8; tj++) {
                int c0 = cm + tj * 8 + 2 * (lane & 3);
                *(float2*)&Ds[r0 * 132 + c0]       = make_float2(c[ti][tj][0], c[ti][tj][1]);
                *(float2*)&Ds[(r0 + 8) * 132 + c0] = make_float2(c[ti][tj][2], c[ti][tj][3]);
            }
        }
        __syncthreads();

        int o = tid >> 2, g = tid & 3;
        {
            const float* xcb = g_xc + (size_t)(b * 64 + o) * N_ + mta * 128;
#pragma unroll 4
            for (int k = 0; k < 32; k++) {
                int m = g * 32 + k;
                float xru = Ds[o * 132 + m] + Ds[(o + 64) * 132 + m];
                Ds[o * 132 + m] = xcb[m] - xru / (1e-9f + cs[m]);
            }
        }
        __syncthreads();

        {
            float bias = b_t[o];
            float psum = 0.f, psq = 0.f;
            float* tout = g_t + (size_t)(b * 64 + o) * N_ + mta * 128;
#pragma unroll
            for (int rep = 0; rep < 2; rep++) {
                int m0 = g * 32 + rep * 16;
                float acc[16];
#pragma unroll
                for (int j = 0; j < 16; j++) acc[j] = 0.f;
#pragma unroll 4
                for (int k = 0; k < 64; k++) {
                    float w = Wts[o * 64 + k];
                    const float4* dr = (const float4*)&Ds[k * 132 + m0];
#pragma unroll
                    for (int q = 0; q < 4; q++) {
                        float4 d4 = dr[q];
                        acc[4*q]   += w * d4.x; acc[4*q+1] += w * d4.y;
                        acc[4*q+2] += w * d4.z; acc[4*q+3] += w * d4.w;
                    }
                }
#pragma unroll
                for (int j = 0; j < 16; j += 4) {
                    float t0 = acc[j] + bias, t1 = acc[j+1] + bias, t2 = acc[j+2] + bias, t3 = acc[j+3] + bias;
                    *(float4*)&tout[m0 + j] = make_float4(t0, t1, t2, t3);
                    psum += t0 + t1 + t2 + t3;
                    psq  += t0*t0 + t1*t1 + t2*t2 + t3*t3;
                }
            }
            float* Rs = (float*)(smc + K3_RED);
            float* Rq = Rs + 256;
            Rs[o * 4 + g] = psum;
            Rq[o * 4 + g] = psq;
            __syncthreads();
            if (tid < 64) {
                float s = Rs[tid*4] + Rs[tid*4+1] + Rs[tid*4+2] + Rs[tid*4+3];
                float q = Rq[tid*4] + Rq[tid*4+1] + Rq[tid*4+2] + Rq[tid*4+3];
                int blk = b * 32 + mta;
                g_part[tid * 256 + blk]            = s;
                g_part[64 * 256 + tid * 256 + blk] = q;
            }
        }
    }
}

// ================= K5: BN stats =================
__global__ void k_bnstats(const float* __restrict__ gamma, const float* __restrict__ beta)
{
    int c = threadIdx.x;
    if (c >= 64) return;
    float s = 0.f, q = 0.f;
    for (int j = 0; j < 256; j++) {
        s += g_part[c * 256 + j];
        q += g_part[64 * 256 + c * 256 + j];
    }
    const float invN = 1.0f / 32768.0f;
    float mean = s * invN;
    float var  = q * invN - mean * mean;
    float sc = gamma[c] * rsqrtf(var + 1e-5f);
    g_bn[c]      = sc;
    g_bn[64 + c] = beta[c] - mean * sc;
}

// ================= K6: out = x_c + relu(scale*t + shift) =================
__global__ void k_final(float* __restrict__ out)
{
    int i4 = blockIdx.x * 256 + threadIdx.x;
    if (i4 >= B_ * C2_ * (N_ / 4)) return;
    int ch = (i4 >> 10) & 63;
    float sc = g_bn[ch], sh = g_bn[64 + ch];
    float4 t  = ((const float4*)g_t)[i4];
    float4 xc = ((const float4*)g_xc)[i4];
    float4 r;
    r.x = xc.x + fmaxf(0.f, sc * t.x + sh);
    r.y = xc.y + fmaxf(0.f, sc * t.y + sh);
    r.z = xc.z + fmaxf(0.f, sc * t.z + sh);
    r.w = xc.w + fmaxf(0.f, sc * t.w + sh);
    ((float4*)out)[i4] = r;
}

// ================= launch =================
extern "C" void kernel_launch(void* const* d_in, const int* in_sizes, int n_in,
                              void* d_out, int out_size)
{
    const float* x     = (const float*)d_in[0];
    const float* w_qk  = (const float*)d_in[1];
    const float* w_v   = (const float*)d_in[2];
    const float* b_v   = (const float*)d_in[3];
    const float* w_x   = (const float*)d_in[4];
    const float* w_t   = (const float*)d_in[5];
    const float* b_t   = (const float*)d_in[6];
    const float* gamma = (const float*)d_in[7];
    const float* beta  = (const float*)d_in[8];
    float* out = (float*)d_out;

    cudaFuncSetAttribute(k_proj,   cudaFuncAttributeMaxDynamicSharedMemorySize, P_SMEM);
    cudaFuncSetAttribute(k_energy, cudaFuncAttributeMaxDynamicSharedMemorySize, K2_SMEM);
    cudaFuncSetAttribute(k_attn,   cudaFuncAttributeMaxDynamicSharedMemorySize, K3_SMEM);

    k_proj    <<<dim3(32, 8), 256, P_SMEM>>>(x, w_qk, w_v, b_v, w_x);
    k_energy  <<<dim3(528, 8), 256, K2_SMEM>>>();
    k_rowav   <<<128, 256>>>();
    k_attn    <<<dim3(16, 8), 256, K3_SMEM>>>(w_t, b_t);
    k_bnstats <<<1, 64>>>(gamma, beta);
    k_final   <<<2048, 256>>>(out);
}

// round 11
// speedup vs baseline: 5.2527x; 1.0345x over previous
#include <cuda_runtime.h>
#include <cuda_bf16.h>
#include <math.h>

#define B_  8
#define C_  128
#define N_  4096
#define C2_ 64

// ---------------- scratch ----------------
__device__ __align__(16) __nv_bfloat16 g_qs[B_*N_*128];    // [b][n][k] k:0-63 hi, 64-127 lo
__device__ __align__(16) float g_v [B_*C2_*N_];
__device__ __align__(16) float g_xc[B_*C2_*N_];
__device__ __align__(16) float g_rspart[B_*32*32*128];     // rowsum partials (b,nt,mt,row)
__device__ __align__(16) __nv_bfloat16 g_invsbf[B_*2*N_];  // [b][hi/lo][n]
__device__ __align__(16) __nv_bfloat16 g_av[B_*128*N_];    // [b][r][n] r:0-63 hi(v*invs), 64-127 lo
__device__ __align__(16) float g_t [B_*C2_*N_];
__device__ __align__(16) float g_part[2*64*256];
__device__ __align__(16) float g_bn[128];
__device__ __align__(16) __nv_bfloat16 g_ph[(size_t)B_*N_*N_];  // hi plane of exp(E), UPPER tiles only
__device__ __align__(16) __nv_bfloat16 g_pl[(size_t)B_*N_*N_];  // lo plane, UPPER tiles only

// ---------------- helpers ----------------
__device__ __forceinline__ unsigned smem_u32(const void* p){
    unsigned a; asm("{ .reg .u64 t; cvta.to.shared.u64 t, %1; cvt.u32.u64 %0, t; }" : "=r"(a) : "l"(p)); return a;
}
__device__ __forceinline__ void ldsm_x4(unsigned* r, unsigned addr){
    asm volatile("ldmatrix.sync.aligned.m8n8.x4.shared.b16 {%0,%1,%2,%3}, [%4];"
        : "=r"(r[0]), "=r"(r[1]), "=r"(r[2]), "=r"(r[3]) : "r"(addr));
}
__device__ __forceinline__ void ldsm_x4_t(unsigned* r, unsigned addr){
    asm volatile("ldmatrix.sync.aligned.m8n8.x4.trans.shared.b16 {%0,%1,%2,%3}, [%4];"
        : "=r"(r[0]), "=r"(r[1]), "=r"(r[2]), "=r"(r[3]) : "r"(addr));
}
__device__ __forceinline__ void mma16816(float* c, const unsigned* a, const unsigned* b){
    asm volatile("mma.sync.aligned.m16n8k16.row.col.f32.bf16.bf16.f32 "
        "{%0,%1,%2,%3}, {%4,%5,%6,%7}, {%8,%9}, {%0,%1,%2,%3};"
        : "+f"(c[0]), "+f"(c[1]), "+f"(c[2]), "+f"(c[3])
        : "r"(a[0]), "r"(a[1]), "r"(a[2]), "r"(a[3]), "r"(b[0]), "r"(b[1]));
}
__device__ __forceinline__ void cp16(unsigned s, const void* g){
    asm volatile("{ .reg .u64 gp; cvta.to.global.u64 gp, %1; cp.async.cg.shared.global [%0], [gp], 16; }"
        :: "r"(s), "l"(g));
}
#define CP_COMMIT() asm volatile("cp.async.commit_group;" ::: "memory")
#define CP_WAIT(n)  asm volatile("cp.async.wait_group %0;" :: "n"(n) : "memory")

__device__ __forceinline__ unsigned packbf(__nv_bfloat16 a, __nv_bfloat16 b){
    return (unsigned)__bfloat16_as_ushort(a) | ((unsigned)__bfloat16_as_ushort(b) << 16);
}

// ================= K1: projections via split-bf16 HMMA =================
// grid (nt=32, b=8), 256 thr. M=192 rows (qk|v|xc), N=128 cols, K=128, 3 passes.
#define P_WH 0
#define P_WL 52224
#define P_XH 104448
#define P_XL 139264
#define P_SMEM 174080
__global__ void __launch_bounds__(256)
k_proj(const float* __restrict__ x, const float* __restrict__ w_qk,
       const float* __restrict__ w_v, const float* __restrict__ b_v,
       const float* __restrict__ w_x)
{
    extern __shared__ char smc[];
    unsigned sb = smem_u32(smc);
    int b = blockIdx.y, nt = blockIdx.x;
    int tid = threadIdx.x, wid = tid >> 5, lane = tid & 31;

    unsigned short* WH = (unsigned short*)(smc + P_WH);
    unsigned short* WL = (unsigned short*)(smc + P_WL);
    for (int i = tid; i < 24576; i += 256) {
        float wv = (i < 8192) ? w_qk[i] : (i < 16384 ? w_v[i - 8192] : w_x[i - 16384]);
        int row = i >> 7, cc = i & 127;
        __nv_bfloat16 h = __float2bfloat16(wv);
        __nv_bfloat16 l = __float2bfloat16(wv - __bfloat162float(h));
        WH[row * 136 + cc] = __bfloat16_as_ushort(h);
        WL[row * 136 + cc] = __bfloat16_as_ushort(l);
    }
    unsigned short* XH = (unsigned short*)(smc + P_XH);
    unsigned short* XL = (unsigned short*)(smc + P_XL);
    const float* xp = x + (size_t)(b * C_) * N_ + nt * 128;
    for (int i = tid; i < 16384; i += 256) {
        int c = i >> 7, n = i & 127;
        float v = xp[(size_t)c * N_ + n];
        __nv_bfloat16 h = __float2bfloat16(v);
        __nv_bfloat16 l = __float2bfloat16(v - __bfloat162float(h));
        XH[c * 136 + n] = __bfloat16_as_ushort(h);
        XL[c * 136 + n] = __bfloat16_as_ushort(l);
    }
    __syncthreads();

    int wn = wid >> 1, wm = wid & 1;
    int rm = wn * 48, cn = wm * 64;
    float c[3][8][4];
#pragma unroll
    for (int ti = 0; ti < 3; ti++)
#pragma unroll
        for (int tj = 0; tj < 8; tj++)
#pragma unroll
            for (int q = 0; q < 4; q++) c[ti][tj][q] = 0.f;

#pragma unroll
    for (int p = 0; p < 3; p++) {
        unsigned wa = sb + ((p == 2) ? P_WL : P_WH);
        unsigned xb = sb + ((p == 1) ? P_XL : P_XH);
#pragma unroll
        for (int ks = 0; ks < 8; ks++) {
            unsigned a[3][4];
#pragma unroll
            for (int ti = 0; ti < 3; ti++)
                ldsm_x4(a[ti], wa + (rm + ti * 16 + (lane & 15)) * 272 + ks * 32 + (lane >> 4) * 16);
#pragma unroll
            for (int tjp = 0; tjp < 4; tjp++) {
                unsigned bb[4];
                ldsm_x4_t(bb, xb + (ks * 16 + (lane & 15)) * 272
                              + (cn + tjp * 16 + ((lane >> 4) << 3)) * 2);
#pragma unroll
                for (int ti = 0; ti < 3; ti++) {
                    mma16816(c[ti][2 * tjp],     a[ti], bb);
                    mma16816(c[ti][2 * tjp + 1], a[ti], bb + 2);
                }
            }
        }
    }
    __syncthreads();

    unsigned short* qstage = (unsigned short*)(smc + P_XH);
#pragma unroll
    for (int ti = 0; ti < 3; ti++) {
        int r0 = rm + ti * 16;
        int r = r0 + (lane >> 2);
#pragma unroll
        for (int tj = 0; tj < 8; tj++) {
            int c0 = cn + tj * 8 + 2 * (lane & 3);
            float v0 = c[ti][tj][0], v1 = c[ti][tj][1], v2 = c[ti][tj][2], v3 = c[ti][tj][3];
            if (r0 < 64) {
                __nv_bfloat16 h0 = __float2bfloat16(v0), h1 = __float2bfloat16(v1);
                __nv_bfloat16 h2 = __float2bfloat16(v2), h3 = __float2bfloat16(v3);
                qstage[c0 * 128 + r]            = __bfloat16_as_ushort(h0);
                qstage[c0 * 128 + 64 + r]       = __bfloat16_as_ushort(__float2bfloat16(v0 - __bfloat162float(h0)));
                qstage[(c0 + 1) * 128 + r]      = __bfloat16_as_ushort(h1);
                qstage[(c0 + 1) * 128 + 64 + r] = __bfloat16_as_ushort(__float2bfloat16(v1 - __bfloat162float(h1)));
                qstage[c0 * 128 + r + 8]            = __bfloat16_as_ushort(h2);
                qstage[c0 * 128 + 64 + r + 8]       = __bfloat16_as_ushort(__float2bfloat16(v2 - __bfloat162float(h2)));
                qstage[(c0 + 1) * 128 + r + 8]      = __bfloat16_as_ushort(h3);
                qstage[(c0 + 1) * 128 + 64 + r + 8] = __bfloat16_as_ushort(__float2bfloat16(v3 - __bfloat162float(h3)));
            } else if (r0 < 128) {
                float ba = b_v[r - 64], bb2 = b_v[r - 56];
                *(float2*)&g_v[(size_t)(b * 64 + r - 64) * N_ + nt * 128 + c0] = make_float2(v0 + ba, v1 + ba);
                *(float2*)&g_v[(size_t)(b * 64 + r - 56) * N_ + nt * 128 + c0] = make_float2(v2 + bb2, v3 + bb2);
            } else {
                *(float2*)&g_xc[(size_t)(b * 64 + r - 128) * N_ + nt * 128 + c0] = make_float2(v0, v1);
                *(float2*)&g_xc[(size_t)(b * 64 + r - 120) * N_ + nt * 128 + c0] = make_float2(v2, v3);
            }
        }
    }
    __syncthreads();
    for (int i = tid; i < 2048; i += 256) {
        int row = i >> 4, cc = i & 15;
        ((uint4*)(g_qs + (size_t)(b * N_ + nt * 128 + row) * 128))[cc] =
            ((const uint4*)(qstage + row * 128))[cc];
    }
}

// ================= K2: symmetric E=Q^T Q, P=exp(E) upper tiles only, rowsums both sides ===
#define K2_AS 0
#define K2_BS 34816
#define K2_RED 0
#define K2_RDT 4096
#define K2_SMEM 69632
__global__ void __launch_bounds__(256, 2)
k_energy()
{
    extern __shared__ char smc[];
    unsigned sb = smem_u32(smc);
    int b = blockIdx.y;
    int tid = threadIdx.x, wid = tid >> 5, lane = tid & 31;

    int u = blockIdx.x, nt = 0;
    while (u >= 32 - nt) { u -= 32 - nt; nt++; }
    int mt = nt + u;

    {
        const uint4* asrc = (const uint4*)(g_qs + (size_t)(b * N_ + nt * 128) * 128);
        const uint4* bsrc = (const uint4*)(g_qs + (size_t)(b * N_ + mt * 128) * 128);
        for (int i = tid; i < 2048; i += 256) {
            int row = i >> 4, cc = i & 15;
            *(uint4*)(smc + K2_AS + row * 272 + cc * 16) = asrc[i];
            *(uint4*)(smc + K2_BS + row * 272 + cc * 16) = bsrc[i];
        }
    }
    __syncthreads();

    int wn = wid >> 1, wm = wid & 1;
    int rn = wn * 32, cm = wm * 64;
    float c[2][8][4];
#pragma unroll
    for (int ti = 0; ti < 2; ti++)
#pragma unroll
        for (int tj = 0; tj < 8; tj++)
#pragma unroll
            for (int q = 0; q < 4; q++) c[ti][tj][q] = 0.f;

    const int qa[3] = {0, 0, 1}, qb[3] = {0, 1, 0};
#pragma unroll
    for (int s = 0; s < 12; s++) {
        int grp = s >> 2, km = (s & 3) * 32;
        int ka = qa[grp] * 128 + km, kb = qb[grp] * 128 + km;
        unsigned a[2][4];
#pragma unroll
        for (int ti = 0; ti < 2; ti++)
            ldsm_x4(a[ti], sb + K2_AS + (rn + ti * 16 + (lane & 15)) * 272 + ka + (lane >> 4) * 16);
#pragma unroll
        for (int tjp = 0; tjp < 4; tjp++) {
            unsigned bb[4];
            ldsm_x4(bb, sb + K2_BS + (cm + tjp * 16 + ((lane >> 4) << 3) + (lane & 7)) * 272
                        + kb + ((lane >> 3) & 1) * 16);
            mma16816(c[0][2*tjp],   a[0], bb);     mma16816(c[1][2*tjp],   a[1], bb);
            mma16816(c[0][2*tjp+1], a[0], bb + 2); mma16816(c[1][2*tjp+1], a[1], bb + 2);
        }
    }

    bool offd = (mt != nt);
    float rsA[2] = {0.f, 0.f}, rsB[2] = {0.f, 0.f};
    float colp0[8], colp1[8];
#pragma unroll
    for (int tj = 0; tj < 8; tj++) { colp0[tj] = 0.f; colp1[tj] = 0.f; }
    size_t prow = (size_t)(b * N_ + nt * 128) * N_ + mt * 128;
#pragma unroll
    for (int ti = 0; ti < 2; ti++) {
        int r0 = rn + ti * 16 + (lane >> 2);
#pragma unroll
        for (int tj = 0; tj < 8; tj++) {
            int c0 = cm + tj * 8 + 2 * (lane & 3);
            float p0 = __expf(c[ti][tj][0]), p1 = __expf(c[ti][tj][1]);
            float p2 = __expf(c[ti][tj][2]), p3 = __expf(c[ti][tj][3]);
            rsA[ti] += p0 + p1;  rsB[ti] += p2 + p3;
            colp0[tj] += p0 + p2; colp1[tj] += p1 + p3;
            __nv_bfloat16 h0 = __float2bfloat16(p0), h1 = __float2bfloat16(p1);
            __nv_bfloat16 h2 = __float2bfloat16(p2), h3 = __float2bfloat16(p3);
            __nv_bfloat16 l0 = __float2bfloat16(p0 - __bfloat162float(h0));
            __nv_bfloat16 l1 = __float2bfloat16(p1 - __bfloat162float(h1));
            __nv_bfloat16 l2 = __float2bfloat16(p2 - __bfloat162float(h2));
            __nv_bfloat16 l3 = __float2bfloat16(p3 - __bfloat162float(h3));
            size_t ba = prow + (size_t)r0 * N_ + c0;
            size_t bc = ba + (size_t)8 * N_;
            *(unsigned*)(g_ph + ba) = packbf(h0, h1);
            *(unsigned*)(g_pl + ba) = packbf(l0, l1);
            *(unsigned*)(g_ph + bc) = packbf(h2, h3);
            *(unsigned*)(g_pl + bc) = packbf(l2, l3);
        }
    }
    if (offd) {
#pragma unroll
        for (int tj = 0; tj < 8; tj++) {
            colp0[tj] += __shfl_xor_sync(0xffffffff, colp0[tj], 4);
            colp0[tj] += __shfl_xor_sync(0xffffffff, colp0[tj], 8);
            colp0[tj] += __shfl_xor_sync(0xffffffff, colp0[tj], 16);
            colp1[tj] += __shfl_xor_sync(0xffffffff, colp1[tj], 4);
            colp1[tj] += __shfl_xor_sync(0xffffffff, colp1[tj], 8);
            colp1[tj] += __shfl_xor_sync(0xffffffff, colp1[tj], 16);
        }
    }
    __syncthreads();

    float* red  = (float*)(smc + K2_RED);
    float* redT = (float*)(smc + K2_RDT);
#pragma unroll
    for (int ti = 0; ti < 2; ti++) {
        int r0 = rn + ti * 16 + (lane >> 2);
        red[r0 * 8 + wm * 4 + (lane & 3)]       = rsA[ti];
        red[(r0 + 8) * 8 + wm * 4 + (lane & 3)] = rsB[ti];
    }
    if (offd && lane < 4) {
#pragma unroll
        for (int tj = 0; tj < 8; tj++) {
            redT[wn * 128 + cm + tj * 8 + 2 * lane]     = colp0[tj];
            redT[wn * 128 + cm + tj * 8 + 2 * lane + 1] = colp1[tj];
        }
    }
    __syncthreads();
    if (tid < 128) {
        float s = 0.f;
#pragma unroll
        for (int j = 0; j < 8; j++) s += red[tid * 8 + j];
        g_rspart[((size_t)(b * 32 + nt) * 32 + mt) * 128 + tid] = s;
        if (offd) {
            float st = redT[tid] + redT[128 + tid] + redT[256 + tid] + redT[384 + tid];
            g_rspart[((size_t)(b * 32 + mt) * 32 + nt) * 128 + tid] = st;
        }
    }
}

// ================= K2.5: rowsum reduce -> invsbf, Av = v*inv split (merged) =================
__global__ void k_rowav()
{
    int idx = blockIdx.x * 256 + threadIdx.x;
    int b = idx >> 12, n = idx & 4095;
    float s = 0.f;
    const float* p = g_rspart + ((size_t)(b * 32 + (n >> 7)) * 32) * 128 + (n & 127);
#pragma unroll
    for (int mt = 0; mt < 32; mt++) s += p[mt * 128];
    float inv = 1.0f / s;
    __nv_bfloat16 ih = __float2bfloat16(inv);
    g_invsbf[(b * 2 + 0) * N_ + n] = ih;
    g_invsbf[(b * 2 + 1) * N_ + n] = __float2bfloat16(inv - __bfloat162float(ih));
    const float* vs = g_v + (size_t)(b * 64) * N_ + n;
    __nv_bfloat16* avh = g_av + (size_t)(b * 128) * N_ + n;
#pragma unroll 4
    for (int o = 0; o < 64; o++) {
        float a = vs[(size_t)o * N_] * inv;
        __nv_bfloat16 h = __float2bfloat16(a);
        avh[(size_t)o * N_]        = h;
        avh[(size_t)(o + 64) * N_] = __float2bfloat16(a - __bfloat162float(h));
    }
}

// ================= K3: D = Av@(Ph+Pl), 512 thr / 16 warp-tiles 32x32, 3-stage cp.async ===
// grid (16, 8); each block: 2 mt tiles of 128 cols, K=4096 x 2 planes.
#define K3T      512
#define K3_WT    0           // 16384
#define K3_CS2   16384       // [4][128] f32
#define K3_CS    18432       // [128] f32
#define K3_STG   21504
#define K3_SSZ   57600       // A 18432 | H 18432 | L 18432 | INV 2304
#define K3_RED   (K3_STG + 69632)    // after Ds(67584): [64][8]x2 f32 = 4096
#define K3_SMEM  (21504 + 3*57600)
__device__ __forceinline__ void k3_issue(unsigned sb, int st, int b, int mta, int ch, int tid)
{
    unsigned s0 = sb + K3_STG + st * K3_SSZ;
    int nb = ch << 6;
    bool tr = (mta > (ch >> 1));
    const __nv_bfloat16* asrc = g_av + (size_t)b * 128 * N_ + nb;
    const __nv_bfloat16 *hsrc, *lsrc;
    if (!tr) {
        hsrc = g_ph + ((size_t)(b * N_ + mta * 128)) * N_ + nb;
        lsrc = g_pl + ((size_t)(b * N_ + mta * 128)) * N_ + nb;
    } else {
        hsrc = g_ph + ((size_t)(b * N_ + nb)) * N_ + mta * 128;
        lsrc = g_pl + ((size_t)(b * N_ + nb)) * N_ + mta * 128;
    }
    for (int i = tid; i < 1024; i += K3T) {
        int ar = i >> 3, ac = i & 7;
        cp16(s0 + ar * 144 + ac * 16, asrc + (size_t)ar * N_ + ac * 8);
        if (!tr) {
            cp16(s0 + 18432 + ar * 144 + ac * 16, hsrc + (size_t)ar * N_ + ac * 8);
            cp16(s0 + 36864 + ar * 144 + ac * 16, lsrc + (size_t)ar * N_ + ac * 8);
        } else {
            int rr = i >> 4, cc = i & 15;
            cp16(s0 + 18432 + rr * 272 + cc * 16, hsrc + (size_t)rr * N_ + cc * 8);
            cp16(s0 + 36864 + rr * 272 + cc * 16, lsrc + (size_t)rr * N_ + cc * 8);
        }
    }
    if (tid < 16) {
        int row = tid >> 3, cc = tid & 7;
        cp16(s0 + 55296 + row * 144 + cc * 16,
             g_invsbf + (size_t)(b * 2 + row) * N_ + nb + cc * 8);
    }
}

__global__ void __launch_bounds__(K3T)
k_attn(const float* __restrict__ w_t, const float* __restrict__ b_t)
{
    extern __shared__ char smc[];
    unsigned sb = smem_u32(smc);
    int b = blockIdx.y;
    int tid = threadIdx.x, wid = tid >> 5, lane = tid & 31;
    float* Wts = (float*)(smc + K3_WT);
    float* cs2 = (float*)(smc + K3_CS2);
    float* cs  = (float*)(smc + K3_CS);

    for (int i = tid; i < 4096; i += K3T) Wts[i] = w_t[i];
    for (int st = 0; st < 3; st++)
        for (int i = tid; i < 504; i += K3T)
            *(unsigned*)(smc + K3_STG + st * K3_SSZ + 55296 + 288 + i * 4) = 0;

    int wn = wid >> 2, wm = wid & 3;        // 16 warps: 4 row groups x 4 col groups
    int rn = wn * 32, cm = wm * 32;

#pragma unroll 1
    for (int half = 0; half < 2; half++) {
        int mta = blockIdx.x * 2 + half;
        float c[2][4][4], ccs[4][4];
#pragma unroll
        for (int tj = 0; tj < 4; tj++) {
#pragma unroll
            for (int q = 0; q < 4; q++) { c[0][tj][q] = 0.f; c[1][tj][q] = 0.f; ccs[tj][q] = 0.f; }
        }
        __syncthreads();
        k3_issue(sb, 0, b, mta, 0, tid); CP_COMMIT();
        k3_issue(sb, 1, b, mta, 1, tid); CP_COMMIT();

        for (int ch = 0; ch < 64; ch++) {
            if (ch + 2 < 64) CP_WAIT(1); else CP_WAIT(0);
            __syncthreads();
            if (ch + 2 < 64) { k3_issue(sb, (ch + 2) % 3, b, mta, ch + 2, tid); CP_COMMIT(); }

            unsigned sA = sb + K3_STG + (ch % 3) * K3_SSZ;
            unsigned sH = sA + 18432, sL = sA + 36864, sI = sA + 55296;
            bool tr = (mta > (ch >> 1));
            if (!tr) {
#pragma unroll
                for (int ks = 0; ks < 4; ks++) {
                    unsigned a[2][4], ainv[4];
                    ldsm_x4(a[0], sA + (rn + (lane & 15)) * 144 + ks * 32 + (lane >> 4) * 16);
                    ldsm_x4(a[1], sA + (rn + 16 + (lane & 15)) * 144 + ks * 32 + (lane >> 4) * 16);
                    bool mine = (ks == wn);
                    if (mine) ldsm_x4(ainv, sI + (lane & 15) * 144 + ks * 32 + (lane >> 4) * 16);
#pragma unroll
                    for (int tj = 0; tj < 4; tj++) {
                        unsigned bb[4];
                        unsigned boff = (cm + tj * 8 + (lane & 7)) * 144 + ks * 32 + ((lane >> 3) & 1) * 16;
                        ldsm_x4(bb, ((lane >> 4) ? sL : sH) + boff);
                        mma16816(c[0][tj], a[0], bb);     mma16816(c[1][tj], a[1], bb);
                        mma16816(c[0][tj], a[0], bb + 2); mma16816(c[1][tj], a[1], bb + 2);
                        if (mine) { mma16816(ccs[tj], ainv, bb); mma16816(ccs[tj], ainv, bb + 2); }
                    }
                }
            } else {
#pragma unroll
                for (int ks = 0; ks < 4; ks++) {
                    unsigned a[2][4], ainv[4];
                    ldsm_x4(a[0], sA + (rn + (lane & 15)) * 144 + ks * 32 + (lane >> 4) * 16);
                    ldsm_x4(a[1], sA + (rn + 16 + (lane & 15)) * 144 + ks * 32 + (lane >> 4) * 16);
                    bool mine = (ks == wn);
                    if (mine) ldsm_x4(ainv, sI + (lane & 15) * 144 + ks * 32 + (lane >> 4) * 16);
#pragma unroll
                    for (int tj = 0; tj < 4; tj++) {
                        unsigned bb[4];
                        unsigned boff = (ks * 16 + (lane & 15)) * 272 + (cm + tj * 8) * 2;
                        ldsm_x4_t(bb, ((lane >> 4) ? sL : sH) + boff);
                        mma16816(c[0][tj], a[0], bb);     mma16816(c[1][tj], a[1], bb);
                        mma16816(c[0][tj], a[0], bb + 2); mma16816(c[1][tj], a[1], bb + 2);
                        if (mine) { mma16816(ccs[tj], ainv, bb); mma16816(ccs[tj], ainv, bb + 2); }
                    }
                }
            }
        }
#pragma unroll
        for (int tj = 0; tj < 4; tj++) {
            float v0 = ccs[tj][0] + __shfl_xor_sync(0xffffffff, ccs[tj][0], 4);
            float v1 = ccs[tj][1] + __shfl_xor_sync(0xffffffff, ccs[tj][1], 4);
            if (lane < 4) {
                cs2[wn * 128 + cm + tj * 8 + 2 * lane]     = v0;
                cs2[wn * 128 + cm + tj * 8 + 2 * lane + 1] = v1;
            }
        }
        __syncthreads();
        if (tid < 128)
            cs[tid] = cs2[tid] + cs2[128 + tid] + cs2[256 + tid] + cs2[384 + tid];
        __syncthreads();

        float* Ds = (float*)(smc + K3_STG);
#pragma unroll
        for (int ti = 0; ti < 2; ti++) {
            int r0 = rn + ti * 16 + (lane >> 2);
#pragma unroll
            for (int tj = 0; tj < 4; tj++) {
                int c0 = cm + tj * 8 + 2 * (lane & 3);
                *(float2*)&Ds[r0 * 132 + c0]       = make_float2(c[ti][tj][0], c[ti][tj][1]);
                *(float2*)&Ds[(r0 + 8) * 132 + c0] = make_float2(c[ti][tj][2], c[ti][tj][3]);
            }
        }
        __syncthreads();

        int o = tid >> 3, g = tid & 7;      // 64 channels x 8 col-groups of 16
        {
            const float* xcb = g_xc + (size_t)(b * 64 + o) * N_ + mta * 128;
#pragma unroll 4
            for (int k = 0; k < 16; k++) {
                int m = g * 16 + k;
                float xru = Ds[o * 132 + m] + Ds[(o + 64) * 132 + m];
                Ds[o * 132 + m] = xcb[m] - xru / (1e-9f + cs[m]);
            }
        }
        __syncthreads();

        {
            float bias = b_t[o];
            float psum = 0.f, psq = 0.f;
            float* tout = g_t + (size_t)(b * 64 + o) * N_ + mta * 128;
            int m0 = g * 16;
            float acc[16];
#pragma unroll
            for (int j = 0; j < 16; j++) acc[j] = 0.f;
#pragma unroll 4
            for (int k = 0; k < 64; k++) {
                float w = Wts[o * 64 + k];
                const float4* dr = (const float4*)&Ds[k * 132 + m0];
#pragma unroll
                for (int q = 0; q < 4; q++) {
                    float4 d4 = dr[q];
                    acc[4*q]   += w * d4.x; acc[4*q+1] += w * d4.y;
                    acc[4*q+2] += w * d4.z; acc[4*q+3] += w * d4.w;
                }
            }
#pragma unroll
            for (int j = 0; j < 16; j += 4) {
                float t0 = acc[j] + bias, t1 = acc[j+1] + bias, t2 = acc[j+2] + bias, t3 = acc[j+3] + bias;
                *(float4*)&tout[m0 + j] = make_float4(t0, t1, t2, t3);
                psum += t0 + t1 + t2 + t3;
                psq  += t0*t0 + t1*t1 + t2*t2 + t3*t3;
            }
            float* Rs = (float*)(smc + K3_RED);
            float* Rq = Rs + 512;
            Rs[o * 8 + g] = psum;
            Rq[o * 8 + g] = psq;
            __syncthreads();
            if (tid < 64) {
                float s = 0.f, q = 0.f;
#pragma unroll
                for (int j = 0; j < 8; j++) { s += Rs[tid * 8 + j]; q += Rq[tid * 8 + j]; }
                int blk = b * 32 + mta;
                g_part[tid * 256 + blk]            = s;
                g_part[64 * 256 + tid * 256 + blk] = q;
            }
        }
    }
}

// ================= K5: BN stats =================
__global__ void k_bnstats(const float* __restrict__ gamma, const float* __restrict__ beta)
{
    int c = threadIdx.x;
    if (c >= 64) return;
    float s = 0.f, q = 0.f;
    for (int j = 0; j < 256; j++) {
        s += g_part[c * 256 + j];
        q += g_part[64 * 256 + c * 256 + j];
    }
    const float invN = 1.0f / 32768.0f;
    float mean = s * invN;
    float var  = q * invN - mean * mean;
    float sc = gamma[c] * rsqrtf(var + 1e-5f);
    g_bn[c]      = sc;
    g_bn[64 + c] = beta[c] - mean * sc;
}

// ================= K6: out = x_c + relu(scale*t + shift) =================
__global__ void k_final(float* __restrict__ out)
{
    int i4 = blockIdx.x * 256 + threadIdx.x;
    if (i4 >= B_ * C2_ * (N_ / 4)) return;
    int ch = (i4 >> 10) & 63;
    float sc = g_bn[ch], sh = g_bn[64 + ch];
    float4 t  = ((const float4*)g_t)[i4];
    float4 xc = ((const float4*)g_xc)[i4];
    float4 r;
    r.x = xc.x + fmaxf(0.f, sc * t.x + sh);
    r.y = xc.y + fmaxf(0.f, sc * t.y + sh);
    r.z = xc.z + fmaxf(0.f, sc * t.z + sh);
    r.w = xc.w + fmaxf(0.f, sc * t.w + sh);
    ((float4*)out)[i4] = r;
}

// ================= launch =================
extern "C" void kernel_launch(void* const* d_in, const int* in_sizes, int n_in,
                              void* d_out, int out_size)
{
    const float* x     = (const float*)d_in[0];
    const float* w_qk  = (const float*)d_in[1];
    const float* w_v   = (const float*)d_in[2];
    const float* b_v   = (const float*)d_in[3];
    const float* w_x   = (const float*)d_in[4];
    const float* w_t   = (const float*)d_in[5];
    const float* b_t   = (const float*)d_in[6];
    const float* gamma = (const float*)d_in[7];
    const float* beta  = (const float*)d_in[8];
    float* out = (float*)d_out;

    cudaFuncSetAttribute(k_proj,   cudaFuncAttributeMaxDynamicSharedMemorySize, P_SMEM);
    cudaFuncSetAttribute(k_energy, cudaFuncAttributeMaxDynamicSharedMemorySize, K2_SMEM);
    cudaFuncSetAttribute(k_attn,   cudaFuncAttributeMaxDynamicSharedMemorySize, K3_SMEM);

    k_proj    <<<dim3(32, 8), 256, P_SMEM>>>(x, w_qk, w_v, b_v, w_x);
    k_energy  <<<dim3(528, 8), 256, K2_SMEM>>>();
    k_rowav   <<<128, 256>>>();
    k_attn    <<<dim3(16, 8), K3T, K3_SMEM>>>(w_t, b_t);
    k_bnstats <<<1, 64>>>(gamma, beta);
    k_final   <<<2048, 256>>>(out);
}